// round 5
// baseline (speedup 1.0000x reference)
#include <cuda_runtime.h>
#include <cuda_bf16.h>
#include <mma.h>
using namespace nvcuda;

#define B_  32
#define T_  64
#define S_  64
#define H_  512
#define D_  512
#define V_  32000
#define G4_ 2048            // 4*H
#define MR_ 2048            // T*B rows

// d_out layout (f32): log_probs [T,B,V], hT [2,B,H], cT [2,B,H], attn [B,S]
#define OFF_HT   ((size_t)T_ * B_ * V_)          // 65,536,000
#define OFF_CT   (OFF_HT + (size_t)2 * B_ * H_)
#define OFF_ATTN (OFF_CT + (size_t)2 * B_ * H_)

// ---------------- device scratch (no runtime allocation allowed) -----------
__device__ float g_pre0[(size_t)MR_ * G4_];          // 16 MB  x@Wih0^T + biases
__device__ float g_hT[2][2][H_ * B_];                // [layer][parity][k*B+b]
__device__ float g_cT[2][H_ * B_];
__device__ float g_qT[H_ * B_];
__device__ float g_ctxT[2 * H_ * B_];                // [ctx ; h_top] transposed
__device__ __nv_bfloat16 g_outs_bf[(size_t)MR_ * H_];        // 2 MB
__device__ __nv_bfloat16 g_wlin_bf[(size_t)V_ * D_];         // 32 MB

__device__ __forceinline__ float sigf(float x) { return 1.f / (1.f + __expf(-x)); }

// ---------------- W_lin fp32 -> bf16 ---------------------------------------
__global__ void k_convert_wlin(const float* __restrict__ w) {
    int i = blockIdx.x * blockDim.x + threadIdx.x;          // over float4s
    if (i < (V_ * D_) / 4) {
        float4 v = reinterpret_cast<const float4*>(w)[i];
        __nv_bfloat162* o = reinterpret_cast<__nv_bfloat162*>(g_wlin_bf);
        o[i * 2]     = __floats2bfloat162_rn(v.x, v.y);
        o[i * 2 + 1] = __floats2bfloat162_rn(v.z, v.w);
    }
}

// ---------------- embed + input projection: pre0 = emb @ Wih0^T + b --------
// C[m][n] = sum_k embedding[tok(m)][k] * Wih0[n][k] + bih0[n] + bhh0[n]
__global__ void k_gemm_pre(const int* __restrict__ tokens,
                           const float* __restrict__ embedding,
                           const float* __restrict__ Wih0,
                           const float* __restrict__ bih0,
                           const float* __restrict__ bhh0) {
    __shared__ float As[64][33];
    __shared__ float Bs[64][33];
    __shared__ int  toks[64];
    const int tid = threadIdx.x;                 // 256 threads
    const int m0 = blockIdx.y * 64, n0 = blockIdx.x * 64;
    if (tid < 64) {
        int m = m0 + tid;
        int t = m >> 5, b = m & 31;
        toks[tid] = tokens[b * T_ + t];
    }
    __syncthreads();
    float acc[4][4] = {};
    const int ty = tid / 16, tx = tid % 16;
    for (int k0 = 0; k0 < D_; k0 += 32) {
#pragma unroll
        for (int it = 0; it < 2; it++) {
            int idx = tid + it * 256;            // 512 float4 slots (64 rows x 8)
            int r = idx >> 3;
            int c = (idx & 7) * 4;
            float4 va = *reinterpret_cast<const float4*>(
                embedding + (size_t)toks[r] * D_ + k0 + c);
            As[r][c] = va.x; As[r][c + 1] = va.y; As[r][c + 2] = va.z; As[r][c + 3] = va.w;
            float4 vb = *reinterpret_cast<const float4*>(
                Wih0 + (size_t)(n0 + r) * D_ + k0 + c);
            Bs[r][c] = vb.x; Bs[r][c + 1] = vb.y; Bs[r][c + 2] = vb.z; Bs[r][c + 3] = vb.w;
        }
        __syncthreads();
#pragma unroll
        for (int kk = 0; kk < 32; kk++) {
            float a[4], b4[4];
#pragma unroll
            for (int i = 0; i < 4; i++) a[i]  = As[ty * 4 + i][kk];
#pragma unroll
            for (int j = 0; j < 4; j++) b4[j] = Bs[tx * 4 + j][kk];
#pragma unroll
            for (int i = 0; i < 4; i++)
#pragma unroll
                for (int j = 0; j < 4; j++) acc[i][j] += a[i] * b4[j];
        }
        __syncthreads();
    }
#pragma unroll
    for (int i = 0; i < 4; i++)
#pragma unroll
        for (int j = 0; j < 4; j++) {
            int m = m0 + ty * 4 + i, n = n0 + tx * 4 + j;
            g_pre0[(size_t)m * G4_ + n] = acc[i][j] + bih0[n] + bhh0[n];
        }
}

// ---------------- init transposed state ------------------------------------
__global__ void k_init(const float* __restrict__ h0, const float* __restrict__ c0) {
    int i = blockIdx.x * blockDim.x + threadIdx.x;   // over B*H
    if (i < B_ * H_) {
        int b = i / H_, k = i % H_;
        g_hT[0][0][k * B_ + b] = h0[i];
        g_hT[1][0][k * B_ + b] = h0[B_ * H_ + i];
        g_cT[0][k * B_ + b]    = c0[i];
        g_cT[1][k * B_ + b]    = c0[B_ * H_ + i];
    }
}

// ---------------- LSTM layer 0 step ----------------------------------------
// warp handles 2 jj values x 4 gates; lane = batch index; full dot in regs.
__global__ void k_lstm0(const float* __restrict__ Whh0, int t, int p) {
    int gw   = (blockIdx.x * blockDim.x + threadIdx.x) >> 5;  // 0..255
    int lane = threadIdx.x & 31;
    int jj0  = gw * 2;
    const float* hin  = g_hT[0][p];
    float*       hout = g_hT[0][p ^ 1];
    float acc[2][4] = {};
    const float* wp[2][4];
#pragma unroll
    for (int q = 0; q < 2; q++)
#pragma unroll
        for (int g = 0; g < 4; g++)
            wp[q][g] = Whh0 + (size_t)(g * H_ + jj0 + q) * H_;
#pragma unroll 2
    for (int k = 0; k < H_; k += 2) {
        float h0v = hin[k * B_ + lane];
        float h1v = hin[(k + 1) * B_ + lane];
#pragma unroll
        for (int q = 0; q < 2; q++)
#pragma unroll
            for (int g = 0; g < 4; g++) {
                float2 wv = *reinterpret_cast<const float2*>(wp[q][g] + k);
                acc[q][g] += h0v * wv.x + h1v * wv.y;
            }
    }
    const float* pre = g_pre0 + (size_t)(t * B_ + lane) * G4_;
#pragma unroll
    for (int q = 0; q < 2; q++) {
        int jj = jj0 + q;
        float gi = sigf(acc[q][0] + pre[jj]);
        float gf = sigf(acc[q][1] + pre[H_ + jj]);
        float gg = tanhf(acc[q][2] + pre[2 * H_ + jj]);
        float go = sigf(acc[q][3] + pre[3 * H_ + jj]);
        float c  = gf * g_cT[0][jj * B_ + lane] + gi * gg;
        g_cT[0][jj * B_ + lane] = c;
        hout[jj * B_ + lane]    = go * tanhf(c);
    }
}

// ---------------- LSTM layer 1 step ----------------------------------------
__global__ void k_lstm1(const float* __restrict__ Wih1, const float* __restrict__ Whh1,
                        const float* __restrict__ bih1, const float* __restrict__ bhh1,
                        int p) {
    int gw   = (blockIdx.x * blockDim.x + threadIdx.x) >> 5;
    int lane = threadIdx.x & 31;
    int jj0  = gw * 2;
    const float* xin  = g_hT[0][p ^ 1];   // layer-0 output of this step
    const float* hin  = g_hT[1][p];
    float*       hout = g_hT[1][p ^ 1];
    float acc[2][4] = {};
    const float* wi[2][4];
    const float* wh[2][4];
#pragma unroll
    for (int q = 0; q < 2; q++)
#pragma unroll
        for (int g = 0; g < 4; g++) {
            wi[q][g] = Wih1 + (size_t)(g * H_ + jj0 + q) * H_;
            wh[q][g] = Whh1 + (size_t)(g * H_ + jj0 + q) * H_;
        }
#pragma unroll 2
    for (int k = 0; k < H_; k += 2) {
        float x0 = xin[k * B_ + lane];
        float x1 = xin[(k + 1) * B_ + lane];
        float h0v = hin[k * B_ + lane];
        float h1v = hin[(k + 1) * B_ + lane];
#pragma unroll
        for (int q = 0; q < 2; q++)
#pragma unroll
            for (int g = 0; g < 4; g++) {
                float2 wa = *reinterpret_cast<const float2*>(wi[q][g] + k);
                float2 wb = *reinterpret_cast<const float2*>(wh[q][g] + k);
                acc[q][g] += x0 * wa.x + x1 * wa.y + h0v * wb.x + h1v * wb.y;
            }
    }
#pragma unroll
    for (int q = 0; q < 2; q++) {
        int jj = jj0 + q;
        float bi = bih1[jj]          + bhh1[jj];
        float bf = bih1[H_ + jj]     + bhh1[H_ + jj];
        float bg = bih1[2 * H_ + jj] + bhh1[2 * H_ + jj];
        float bo = bih1[3 * H_ + jj] + bhh1[3 * H_ + jj];
        float gi = sigf(acc[q][0] + bi);
        float gf = sigf(acc[q][1] + bf);
        float gg = tanhf(acc[q][2] + bg);
        float go = sigf(acc[q][3] + bo);
        float c  = gf * g_cT[1][jj * B_ + lane] + gi * gg;
        g_cT[1][jj * B_ + lane] = c;
        hout[jj * B_ + lane]    = go * tanhf(c);
    }
}

// ---------------- attention: q = h_top @ W_attn_in^T ------------------------
__global__ void k_attn_q(const float* __restrict__ Wq, int p) {
    int gw   = (blockIdx.x * blockDim.x + threadIdx.x) >> 5;  // 0..127
    int lane = threadIdx.x & 31;
    int i0   = gw * 4;
    const float* hin = g_hT[1][p ^ 1];
    float acc[4] = {};
#pragma unroll 2
    for (int k = 0; k < H_; k += 2) {
        float h0v = hin[k * B_ + lane];
        float h1v = hin[(k + 1) * B_ + lane];
#pragma unroll
        for (int r = 0; r < 4; r++) {
            float2 wv = *reinterpret_cast<const float2*>(Wq + (size_t)(i0 + r) * H_ + k);
            acc[r] += h0v * wv.x + h1v * wv.y;
        }
    }
#pragma unroll
    for (int r = 0; r < 4; r++) g_qT[(i0 + r) * B_ + lane] = acc[r];
}

// ---------------- attention: scores + softmax + context --------------------
__global__ void k_attn_sm(const float* __restrict__ context, int p,
                          float* __restrict__ attn_dst) {
    __shared__ float qs[H_];
    __shared__ float sc[S_];
    __shared__ float att[S_];
    const int b = blockIdx.x, tid = threadIdx.x;
    const float* hin  = g_hT[1][p ^ 1];
    const float* ctxb = context + (size_t)b * S_ * H_;
    for (int i = tid; i < H_; i += blockDim.x) qs[i] = g_qT[i * B_ + b];
    __syncthreads();
    int warp = tid >> 5, lane = tid & 31;
    for (int s = warp; s < S_; s += 8) {
        float a = 0.f;
        for (int h = lane; h < H_; h += 32) a += ctxb[s * H_ + h] * qs[h];
#pragma unroll
        for (int off = 16; off; off >>= 1) a += __shfl_xor_sync(0xffffffffu, a, off);
        if (lane == 0) sc[s] = a;
    }
    __syncthreads();
    if (tid < 32) {
        float v0 = sc[tid], v1 = sc[tid + 32];
        float m = fmaxf(v0, v1);
#pragma unroll
        for (int off = 16; off; off >>= 1) m = fmaxf(m, __shfl_xor_sync(0xffffffffu, m, off));
        float e0 = __expf(v0 - m), e1 = __expf(v1 - m);
        float s2 = e0 + e1;
#pragma unroll
        for (int off = 16; off; off >>= 1) s2 += __shfl_xor_sync(0xffffffffu, s2, off);
        float inv = 1.f / s2;
        att[tid] = e0 * inv; att[tid + 32] = e1 * inv;
        if (attn_dst) {
            attn_dst[b * S_ + tid]      = e0 * inv;
            attn_dst[b * S_ + tid + 32] = e1 * inv;
        }
    }
    __syncthreads();
    for (int h = tid; h < H_; h += blockDim.x) {
        float a = 0.f;
#pragma unroll 4
        for (int s = 0; s < S_; s++) a += att[s] * ctxb[s * H_ + h];
        g_ctxT[h * B_ + b] = a;
    }
    for (int h = tid; h < H_; h += blockDim.x)
        g_ctxT[(H_ + h) * B_ + b] = hin[h * B_ + b];
}

// ---------------- attention output -> outs_bf[t] ----------------------------
__global__ void k_attn_out(const float* __restrict__ Wo, int t) {
    int gw   = (blockIdx.x * blockDim.x + threadIdx.x) >> 5;  // 0..127
    int lane = threadIdx.x & 31;
    int i0   = gw * 4;
    float acc[4] = {};
#pragma unroll 2
    for (int k = 0; k < 2 * H_; k += 2) {
        float c0 = g_ctxT[k * B_ + lane];
        float c1 = g_ctxT[(k + 1) * B_ + lane];
#pragma unroll
        for (int r = 0; r < 4; r++) {
            float2 wv = *reinterpret_cast<const float2*>(Wo + (size_t)(i0 + r) * (2 * H_) + k);
            acc[r] += c0 * wv.x + c1 * wv.y;
        }
    }
#pragma unroll
    for (int r = 0; r < 4; r++)
        g_outs_bf[(size_t)(t * B_ + lane) * H_ + i0 + r] = __float2bfloat16(tanhf(acc[r]));
}

// ---------------- final state write-out ------------------------------------
__global__ void k_final(float* __restrict__ out) {
    int i = blockIdx.x * blockDim.x + threadIdx.x;   // over B*H
    if (i < B_ * H_) {
        int b = i / H_, k = i % H_;
        out[OFF_HT + i]            = g_hT[0][0][k * B_ + b];
        out[OFF_HT + B_ * H_ + i]  = g_hT[1][0][k * B_ + b];
        out[OFF_CT + i]            = g_cT[0][k * B_ + b];
        out[OFF_CT + B_ * H_ + i]  = g_cT[1][k * B_ + b];
    }
}

// ---------------- vocab GEMM: logits = outs_bf @ wlin_bf^T ------------------
// C [2048, 32000] fp32, block tile 128x128, 8 warps (2x4), warp tile 64x32
__global__ void k_wmma(float* __restrict__ C) {
    __shared__ __align__(16) __nv_bfloat16 As[128 * 16];
    __shared__ __align__(16) __nv_bfloat16 Bs[128 * 16];
    const int m0 = blockIdx.y * 128, n0 = blockIdx.x * 128;
    const int tid = threadIdx.x;                  // 256
    const int wid = tid >> 5;
    const int wm = (wid >> 2) * 64, wn = (wid & 3) * 32;
    wmma::fragment<wmma::accumulator, 16, 16, 16, float> acc[4][2];
#pragma unroll
    for (int i = 0; i < 4; i++)
#pragma unroll
        for (int j = 0; j < 2; j++) wmma::fill_fragment(acc[i][j], 0.f);
    const int r = tid >> 1;
    const int c = (tid & 1) * 8;
    for (int k0 = 0; k0 < D_; k0 += 16) {
        *reinterpret_cast<uint4*>(&As[r * 16 + c]) =
            *reinterpret_cast<const uint4*>(&g_outs_bf[(size_t)(m0 + r) * D_ + k0 + c]);
        *reinterpret_cast<uint4*>(&Bs[r * 16 + c]) =
            *reinterpret_cast<const uint4*>(&g_wlin_bf[(size_t)(n0 + r) * D_ + k0 + c]);
        __syncthreads();
        wmma::fragment<wmma::matrix_b, 16, 16, 16, __nv_bfloat16, wmma::col_major> bf[2];
#pragma unroll
        for (int j = 0; j < 2; j++)
            wmma::load_matrix_sync(bf[j], &Bs[(wn + j * 16) * 16], 16);
#pragma unroll
        for (int i = 0; i < 4; i++) {
            wmma::fragment<wmma::matrix_a, 16, 16, 16, __nv_bfloat16, wmma::row_major> af;
            wmma::load_matrix_sync(af, &As[(wm + i * 16) * 16], 16);
#pragma unroll
            for (int j = 0; j < 2; j++) wmma::mma_sync(acc[i][j], af, bf[j], acc[i][j]);
        }
        __syncthreads();
    }
#pragma unroll
    for (int i = 0; i < 4; i++)
#pragma unroll
        for (int j = 0; j < 2; j++)
            wmma::store_matrix_sync(C + (size_t)(m0 + wm + i * 16) * V_ + n0 + wn + j * 16,
                                    acc[i][j], V_, wmma::mem_row_major);
}

// ---------------- log_softmax (adds b_lin, in-place over d_out rows) --------
__global__ void k_logsoftmax(float* __restrict__ logits, const float* __restrict__ b_lin) {
    const int row = blockIdx.x;
    float* p = logits + (size_t)row * V_;
    const int tid = threadIdx.x;
    float m = -1e30f, s = 0.f;
    for (int v = tid; v < V_; v += 256) {
        float x = p[v] + b_lin[v];
        if (x > m) { s = s * __expf(m - x) + 1.f; m = x; }
        else       { s += __expf(x - m); }
    }
    __shared__ float sm[256], ss[256];
    sm[tid] = m; ss[tid] = s;
    __syncthreads();
    for (int off = 128; off; off >>= 1) {
        if (tid < off) {
            float m2 = sm[tid + off], s2 = ss[tid + off];
            float M = fmaxf(sm[tid], m2);
            ss[tid] = ss[tid] * __expf(sm[tid] - M) + s2 * __expf(m2 - M);
            sm[tid] = M;
        }
        __syncthreads();
    }
    float lse = sm[0] + logf(ss[0]);
    for (int v = tid; v < V_; v += 256)
        p[v] = p[v] + b_lin[v] - lse;
}

// ---------------- host driver ----------------------------------------------
extern "C" void kernel_launch(void* const* d_in, const int* in_sizes, int n_in,
                              void* d_out, int out_size) {
    const int*   tokens     = (const int*)d_in[0];
    const float* h0         = (const float*)d_in[1];
    const float* c0         = (const float*)d_in[2];
    const float* context    = (const float*)d_in[3];
    const float* embedding  = (const float*)d_in[4];
    const float* Wih        = (const float*)d_in[5];
    const float* Whh        = (const float*)d_in[6];
    const float* bih        = (const float*)d_in[7];
    const float* bhh        = (const float*)d_in[8];
    const float* W_attn_in  = (const float*)d_in[9];
    const float* W_attn_out = (const float*)d_in[10];
    const float* W_lin      = (const float*)d_in[11];
    const float* b_lin      = (const float*)d_in[12];
    float* out = (float*)d_out;

    k_convert_wlin<<<(V_ * D_ / 4 + 255) / 256, 256>>>(W_lin);
    k_gemm_pre<<<dim3(G4_ / 64, MR_ / 64), 256>>>(tokens, embedding, Wih, bih, bhh);
    k_init<<<(B_ * H_ + 255) / 256, 256>>>(h0, c0);

    const float* Wih1 = Wih + (size_t)G4_ * D_;
    const float* Whh1 = Whh + (size_t)G4_ * H_;
    const float* bih1 = bih + G4_;
    const float* bhh1 = bhh + G4_;

    for (int t = 0; t < T_; t++) {
        int p = t & 1;
        k_lstm0<<<64, 128>>>(Whh, t, p);
        k_lstm1<<<64, 128>>>(Wih1, Whh1, bih1, bhh1, p);
        k_attn_q<<<32, 128>>>(W_attn_in, p);
        k_attn_sm<<<32, 256>>>(context, p, (t == T_ - 1) ? (out + OFF_ATTN) : nullptr);
        k_attn_out<<<32, 128>>>(W_attn_out, t);
    }

    k_final<<<(B_ * H_ + 255) / 256, 256>>>(out);
    k_wmma<<<dim3(V_ / 128, MR_ / 128), 256>>>(out);
    k_logsoftmax<<<MR_, 256>>>(out, b_lin);
}

// round 7
// speedup vs baseline: 8.3246x; 8.3246x over previous
#include <cuda_runtime.h>
#include <cuda_bf16.h>
#include <mma.h>
using namespace nvcuda;

#define B_  32
#define T_  64
#define S_  64
#define H_  512
#define D_  512
#define V_  32000
#define G4_ 2048            // 4*H
#define MR_ 2048            // T*B rows

#define CTAS_ 128
#define UPC_  4             // units per CTA (both layers)

// d_out layout (f32): log_probs [T,B,V], hT [2,B,H], cT [2,B,H], attn [B,S]
#define OFF_HT   ((size_t)T_ * B_ * V_)
#define OFF_CT   (OFF_HT + (size_t)2 * B_ * H_)
#define OFF_ATTN (OFF_CT + (size_t)2 * B_ * H_)

// ---------------- device scratch -------------------------------------------
__device__ float g_pre0[(size_t)T_ * G4_ * B_];       // [t][gate_row][b]  16MB
__device__ float g_c2[(size_t)B_ * S_ * H_];          // context @ W_attn_in 4MB
__device__ float4 g_h04[2][(H_ / 4) * B_];            // h layer0, k4 layout
__device__ float4 g_h14[2][(H_ / 4) * B_];            // h layer1, k4 layout
__device__ float4 g_cat4[(2 * H_ / 4) * B_];          // [ctx ; h1] k4 layout
__device__ __nv_bfloat16 g_outs_bf[(size_t)MR_ * H_];
__device__ __nv_bfloat16 g_wlin_bf[(size_t)V_ * D_];
__device__ unsigned g_bar;

__device__ __forceinline__ float sigf(float x) { return 1.f / (1.f + __expf(-x)); }

__global__ void k_reset() { g_bar = 0u; }

// ---------------- W_lin fp32 -> bf16 ---------------------------------------
__global__ void k_convert_wlin(const float* __restrict__ w) {
    int i = blockIdx.x * blockDim.x + threadIdx.x;
    if (i < (V_ * D_) / 4) {
        float4 v = reinterpret_cast<const float4*>(w)[i];
        __nv_bfloat162* o = reinterpret_cast<__nv_bfloat162*>(g_wlin_bf);
        o[i * 2]     = __floats2bfloat162_rn(v.x, v.y);
        o[i * 2 + 1] = __floats2bfloat162_rn(v.z, v.w);
    }
}

// ---------------- embed + input projection: pre0 = emb @ Wih0^T + b --------
// stored as g_pre0[t][n][b]
__global__ void k_gemm_pre(const int* __restrict__ tokens,
                           const float* __restrict__ embedding,
                           const float* __restrict__ Wih0,
                           const float* __restrict__ bih0,
                           const float* __restrict__ bhh0) {
    __shared__ float As[64][33];
    __shared__ float Bs[64][33];
    __shared__ int  toks[64];
    const int tid = threadIdx.x;                 // 256 threads
    const int m0 = blockIdx.y * 64, n0 = blockIdx.x * 64;
    if (tid < 64) {
        int m = m0 + tid;
        int t = m >> 5, b = m & 31;
        toks[tid] = tokens[b * T_ + t];
    }
    __syncthreads();
    float acc[4][4] = {};
    const int ty = tid / 16, tx = tid % 16;
    for (int k0 = 0; k0 < D_; k0 += 32) {
#pragma unroll
        for (int it = 0; it < 2; it++) {
            int idx = tid + it * 256;            // 512 float4 slots (64 rows x 8)
            int r = idx >> 3;
            int c = (idx & 7) * 4;
            float4 va = *reinterpret_cast<const float4*>(
                embedding + (size_t)toks[r] * D_ + k0 + c);
            As[r][c] = va.x; As[r][c + 1] = va.y; As[r][c + 2] = va.z; As[r][c + 3] = va.w;
            float4 vb = *reinterpret_cast<const float4*>(
                Wih0 + (size_t)(n0 + r) * D_ + k0 + c);
            Bs[r][c] = vb.x; Bs[r][c + 1] = vb.y; Bs[r][c + 2] = vb.z; Bs[r][c + 3] = vb.w;
        }
        __syncthreads();
#pragma unroll
        for (int kk = 0; kk < 32; kk++) {
            float a[4], b4[4];
#pragma unroll
            for (int i = 0; i < 4; i++) a[i]  = As[ty * 4 + i][kk];
#pragma unroll
            for (int j = 0; j < 4; j++) b4[j] = Bs[tx * 4 + j][kk];
#pragma unroll
            for (int i = 0; i < 4; i++)
#pragma unroll
                for (int j = 0; j < 4; j++) acc[i][j] += a[i] * b4[j];
        }
        __syncthreads();
    }
#pragma unroll
    for (int i = 0; i < 4; i++)
#pragma unroll
        for (int j = 0; j < 4; j++) {
            int m = m0 + ty * 4 + i, n = n0 + tx * 4 + j;
            int t = m >> 5, b = m & 31;
            g_pre0[((size_t)t * G4_ + n) * B_ + b] = acc[i][j] + bih0[n] + bhh0[n];
        }
}

// ---------------- C2 = context @ W_attn_in  (A[2048,512] @ B[512,512]) ------
// C2[m][n] = sum_j A[m][j] * Wq[j][n]   (Wq row-major [H][H])
__global__ void k_c2(const float* __restrict__ A, const float* __restrict__ Wq) {
    __shared__ float As[64][65];          // 64x64 k-tile, padded stride
    __shared__ float Bs[64][65];
    const int tid = threadIdx.x;
    const int m0 = blockIdx.y * 64, n0 = blockIdx.x * 64;
    float acc[4][4] = {};
    const int ty = tid / 16, tx = tid % 16;
    for (int k0 = 0; k0 < H_; k0 += 64) {
#pragma unroll
        for (int it = 0; it < 4; it++) {
            int idx = tid + it * 256;            // 1024 float4 slots (64 x 16)
            int r = idx >> 4;
            int c = (idx & 15) * 4;
            float4 va = *reinterpret_cast<const float4*>(
                A + (size_t)(m0 + r) * H_ + k0 + c);
            As[r][c] = va.x; As[r][c + 1] = va.y; As[r][c + 2] = va.z; As[r][c + 3] = va.w;
            float4 vb = *reinterpret_cast<const float4*>(
                Wq + (size_t)(k0 + r) * H_ + n0 + c);
            Bs[r][c] = vb.x; Bs[r][c + 1] = vb.y; Bs[r][c + 2] = vb.z; Bs[r][c + 3] = vb.w;
        }
        __syncthreads();
#pragma unroll
        for (int kk = 0; kk < 64; kk++) {
            float a[4], b4[4];
#pragma unroll
            for (int i = 0; i < 4; i++) a[i]  = As[ty * 4 + i][kk];
#pragma unroll
            for (int j = 0; j < 4; j++) b4[j] = Bs[kk][tx * 4 + j];
#pragma unroll
            for (int i = 0; i < 4; i++)
#pragma unroll
                for (int j = 0; j < 4; j++) acc[i][j] += a[i] * b4[j];
        }
        __syncthreads();
    }
#pragma unroll
    for (int i = 0; i < 4; i++)
#pragma unroll
        for (int j = 0; j < 4; j++)
            g_c2[(size_t)(m0 + ty * 4 + i) * H_ + n0 + tx * 4 + j] = acc[i][j];
}

// ---------------- persistent scan kernel -----------------------------------
// SMEM float offsets
#define W0S_OFF   0                         // 16*512
#define W1S_OFF   8192                      // 16*1024
#define WOS_OFF   24576                     // 4*1024
#define STAGE_OFF 28672                     // 4096 float4 (16384 floats)
#define GBUF_OFF  45056                     // 16*32
#define CB_OFF    45568                     // 2*4*32
#define B1_OFF    45824                     // 16
#define PART_OFF  45840                     // 8*32
#define SMEM_FLOATS 46096
#define SMEM_BYTES  (SMEM_FLOATS * 4)

__device__ __forceinline__ void gridbar(unsigned target) {
    __threadfence();
    __syncthreads();
    if (threadIdx.x == 0) {
        atomicAdd(&g_bar, 1u);
        volatile unsigned* vb = &g_bar;
        while (*vb < target) { }
    }
    __syncthreads();
}

__global__ void __launch_bounds__(256, 1)
k_scan(const float* __restrict__ Whh0, const float* __restrict__ Wih1,
       const float* __restrict__ Whh1, const float* __restrict__ bih,
       const float* __restrict__ bhh, const float* __restrict__ context,
       const float* __restrict__ Wout, const float* __restrict__ h0in,
       const float* __restrict__ c0in, float* __restrict__ out) {
    extern __shared__ float sm[];
    float*  W0s   = sm + W0S_OFF;
    float*  W1s   = sm + W1S_OFF;
    float*  Wos   = sm + WOS_OFF;
    float4* stage4 = reinterpret_cast<float4*>(sm + STAGE_OFF);
    float*  gbuf  = sm + GBUF_OFF;
    float*  cb    = sm + CB_OFF;
    float*  bias1 = sm + B1_OFF;
    float*  part  = sm + PART_OFF;

    const int cta = blockIdx.x;
    const int tid = threadIdx.x;
    const int w   = tid >> 5;
    const int lane = tid & 31;
    const int u0  = cta * UPC_;

    // -------- prologue: weights -> SMEM -----------------------------------
    for (int idx = tid; idx < 16 * 128; idx += 256) {
        int r = idx >> 7, kq = idx & 127;
        int row = ((r >> 2) * H_) + u0 + (r & 3);
        reinterpret_cast<float4*>(W0s)[r * 128 + kq] =
            *reinterpret_cast<const float4*>(Whh0 + (size_t)row * H_ + kq * 4);
    }
    for (int idx = tid; idx < 16 * 256; idx += 256) {
        int r = idx >> 8, kq = idx & 255;
        int row = ((r >> 2) * H_) + u0 + (r & 3);
        const float* src = (kq < 128)
            ? (Wih1 + (size_t)row * H_ + kq * 4)
            : (Whh1 + (size_t)row * H_ + (kq - 128) * 4);
        reinterpret_cast<float4*>(W1s)[r * 256 + kq] =
            *reinterpret_cast<const float4*>(src);
    }
    for (int idx = tid; idx < 4 * 256; idx += 256) {
        int r = idx >> 8, kq = idx & 255;
        reinterpret_cast<float4*>(Wos)[r * 256 + kq] =
            *reinterpret_cast<const float4*>(Wout + (size_t)(u0 + r) * (2 * H_) + kq * 4);
    }
    if (tid < 16) {
        int row = ((tid >> 2) * H_) + u0 + (tid & 3);
        bias1[tid] = bih[G4_ + row] + bhh[G4_ + row];
    }
    {
        int l = tid >> 7, ul = (tid >> 5) & 3, b = tid & 31;
        cb[tid] = c0in[(size_t)l * B_ * H_ + (size_t)b * H_ + u0 + ul];
    }
    if (tid < 32) {
        int b = tid;
        float4 v0, v1;
        v0.x = h0in[(size_t)b * H_ + u0 + 0];
        v0.y = h0in[(size_t)b * H_ + u0 + 1];
        v0.z = h0in[(size_t)b * H_ + u0 + 2];
        v0.w = h0in[(size_t)b * H_ + u0 + 3];
        v1.x = h0in[(size_t)B_ * H_ + b * H_ + u0 + 0];
        v1.y = h0in[(size_t)B_ * H_ + b * H_ + u0 + 1];
        v1.z = h0in[(size_t)B_ * H_ + b * H_ + u0 + 2];
        v1.w = h0in[(size_t)B_ * H_ + b * H_ + u0 + 3];
        __stcg(&g_h04[0][cta * 32 + b], v0);
        __stcg(&g_h14[0][cta * 32 + b], v1);
    }
    unsigned nbar = 0;
    gridbar(++nbar * CTAS_);

    // -------- main scan ----------------------------------------------------
    for (int t = 0; t < T_; t++) {
        const int p = t & 1;
        const float4* h0old = g_h04[p];
        float4*       h0new = g_h04[p ^ 1];
        const float4* h1old = g_h14[p];
        float4*       h1new = g_h14[p ^ 1];

        // ===== layer 0 =====
        for (int i = tid; i < 4096; i += 256) stage4[i] = __ldcg(&h0old[i]);
        __syncthreads();
        {
            const float4* w0 = reinterpret_cast<const float4*>(W0s + (2 * w) * H_);
            const float4* w1 = reinterpret_cast<const float4*>(W0s + (2 * w + 1) * H_);
            float a0 = 0.f, b0 = 0.f, a1 = 0.f, b1 = 0.f;
#pragma unroll 4
            for (int kq = 0; kq < 128; kq++) {
                float4 h = stage4[kq * 32 + lane];
                float4 x0 = w0[kq], x1 = w1[kq];
                a0 += x0.x * h.x + x0.y * h.y;  b0 += x0.z * h.z + x0.w * h.w;
                a1 += x1.x * h.x + x1.y * h.y;  b1 += x1.z * h.z + x1.w * h.w;
            }
            gbuf[(2 * w) * 32 + lane]     = a0 + b0;
            gbuf[(2 * w + 1) * 32 + lane] = a1 + b1;
        }
        __syncthreads();
        if (tid < 128) {
            int ul = tid >> 5, b = tid & 31, u = u0 + ul;
            const float* pre = g_pre0 + (size_t)t * G4_ * B_;
            float gi = sigf(gbuf[(0  + ul) * 32 + b] + __ldg(&pre[((size_t)0 * H_ + u) * B_ + b]));
            float gf = sigf(gbuf[(4  + ul) * 32 + b] + __ldg(&pre[((size_t)1 * H_ + u) * B_ + b]));
            float gg = tanhf(gbuf[(8  + ul) * 32 + b] + __ldg(&pre[((size_t)2 * H_ + u) * B_ + b]));
            float go = sigf(gbuf[(12 + ul) * 32 + b] + __ldg(&pre[((size_t)3 * H_ + u) * B_ + b]));
            float c = gf * cb[ul * 32 + b] + gi * gg;
            cb[ul * 32 + b] = c;
            float h = go * tanhf(c);
            __stcg(&reinterpret_cast<float*>(h0new)[(cta * 32 + b) * 4 + ul], h);
            if (t == T_ - 1) {
                out[OFF_HT + (size_t)b * H_ + u] = h;
                out[OFF_CT + (size_t)b * H_ + u] = c;
            }
        }
        gridbar(++nbar * CTAS_);

        // ===== layer 1 (two K passes: x = h0new, then h1old) =====
        {
            const float4* wr0 = reinterpret_cast<const float4*>(W1s + (2 * w) * (2 * H_));
            const float4* wr1 = reinterpret_cast<const float4*>(W1s + (2 * w + 1) * (2 * H_));
            float a0 = 0.f, b0 = 0.f, a1 = 0.f, b1 = 0.f;
            for (int pass = 0; pass < 2; pass++) {
                const float4* src = pass ? h1old : (const float4*)h0new;
                for (int i = tid; i < 4096; i += 256) stage4[i] = __ldcg(&src[i]);
                __syncthreads();
                const float4* p0 = wr0 + pass * 128;
                const float4* p1 = wr1 + pass * 128;
#pragma unroll 4
                for (int kq = 0; kq < 128; kq++) {
                    float4 h = stage4[kq * 32 + lane];
                    float4 x0 = p0[kq], x1 = p1[kq];
                    a0 += x0.x * h.x + x0.y * h.y;  b0 += x0.z * h.z + x0.w * h.w;
                    a1 += x1.x * h.x + x1.y * h.y;  b1 += x1.z * h.z + x1.w * h.w;
                }
                __syncthreads();
            }
            gbuf[(2 * w) * 32 + lane]     = a0 + b0;
            gbuf[(2 * w + 1) * 32 + lane] = a1 + b1;
        }
        __syncthreads();
        if (tid < 128) {
            int ul = tid >> 5, b = tid & 31, u = u0 + ul;
            float gi = sigf(gbuf[(0  + ul) * 32 + b] + bias1[0  + ul]);
            float gf = sigf(gbuf[(4  + ul) * 32 + b] + bias1[4  + ul]);
            float gg = tanhf(gbuf[(8  + ul) * 32 + b] + bias1[8  + ul]);
            float go = sigf(gbuf[(12 + ul) * 32 + b] + bias1[12 + ul]);
            float c = gf * cb[128 + ul * 32 + b] + gi * gg;
            cb[128 + ul * 32 + b] = c;
            float h = go * tanhf(c);
            __stcg(&reinterpret_cast<float*>(h1new)[(cta * 32 + b) * 4 + ul], h);
            if (t == T_ - 1) {
                out[OFF_HT + (size_t)B_ * H_ + (size_t)b * H_ + u] = h;
                out[OFF_CT + (size_t)B_ * H_ + (size_t)b * H_ + u] = c;
            }
        }
        gridbar(++nbar * CTAS_);

        // ===== attention (CTAs 0..31, one batch element each) =====
        if (cta < B_) {
            float* qs  = sm + STAGE_OFF;       // 512
            float* sc  = qs + 512;             // 64
            float* att = sc + 64;              // 64
            for (int q = tid; q < 128; q += 256) {
                float4 v = __ldcg(&h1new[q * 32 + cta]);
                reinterpret_cast<float4*>(qs)[q] = v;
            }
            __syncthreads();
            for (int s = w; s < S_; s += 8) {
                const float* c2 = g_c2 + (size_t)(cta * S_ + s) * H_;
                float a = 0.f;
                for (int k = lane; k < H_; k += 32) a += c2[k] * qs[k];
#pragma unroll
                for (int off = 16; off; off >>= 1) a += __shfl_xor_sync(0xffffffffu, a, off);
                if (lane == 0) sc[s] = a;
            }
            __syncthreads();
            if (tid < 32) {
                float v0 = sc[tid], v1 = sc[tid + 32];
                float m = fmaxf(v0, v1);
#pragma unroll
                for (int off = 16; off; off >>= 1) m = fmaxf(m, __shfl_xor_sync(0xffffffffu, m, off));
                float e0 = __expf(v0 - m), e1 = __expf(v1 - m);
                float s2 = e0 + e1;
#pragma unroll
                for (int off = 16; off; off >>= 1) s2 += __shfl_xor_sync(0xffffffffu, s2, off);
                float inv = 1.f / s2;
                att[tid] = e0 * inv; att[tid + 32] = e1 * inv;
                if (t == T_ - 1) {
                    out[OFF_ATTN + cta * S_ + tid]      = e0 * inv;
                    out[OFF_ATTN + cta * S_ + tid + 32] = e1 * inv;
                }
            }
            __syncthreads();
            for (int h = tid; h < H_; h += 256) {
                float a = 0.f;
                const float* cx = context + (size_t)cta * S_ * H_ + h;
#pragma unroll 8
                for (int s = 0; s < S_; s++) a += att[s] * cx[(size_t)s * H_];
                __stcg(&reinterpret_cast<float*>(g_cat4)[((h >> 2) * 32 + cta) * 4 + (h & 3)], a);
                int h2 = H_ + h;
                __stcg(&reinterpret_cast<float*>(g_cat4)[((h2 >> 2) * 32 + cta) * 4 + (h2 & 3)], qs[h]);
            }
        }
        gridbar(++nbar * CTAS_);

        // ===== attention-out: warp = (row = w&3, khalf-sub = w>>2) =====
        {
            float oa = 0.f, ob = 0.f;
            const int row = w & 3, sub = w >> 2;
            for (int half = 0; half < 2; half++) {
                for (int i = tid; i < 4096; i += 256)
                    stage4[i] = __ldcg(&g_cat4[half * 4096 + i]);
                __syncthreads();
                const float4* wr = reinterpret_cast<const float4*>(Wos + row * (2 * H_) + half * H_);
                const int i0 = sub * 64;
#pragma unroll 4
                for (int i = 0; i < 64; i++) {
                    float4 h = stage4[(i0 + i) * 32 + lane];
                    float4 x = wr[i0 + i];
                    oa += x.x * h.x + x.y * h.y;
                    ob += x.z * h.z + x.w * h.w;
                }
                __syncthreads();
            }
            part[w * 32 + lane] = oa + ob;
        }
        __syncthreads();
        if (tid < 128) {
            int r = tid >> 5, b = tid & 31;
            float v = tanhf(part[r * 32 + b] + part[(r + 4) * 32 + b]);
            g_outs_bf[((size_t)t * B_ + b) * H_ + u0 + r] = __float2bfloat16(v);
        }
        __syncthreads();   // protect stage4 before next step's restage
    }
}

// ---------------- vocab GEMM: logits = outs_bf @ wlin_bf^T ------------------
__global__ void k_wmma(float* __restrict__ C) {
    __shared__ __align__(16) __nv_bfloat16 As[128 * 16];
    __shared__ __align__(16) __nv_bfloat16 Bs[128 * 16];
    const int m0 = blockIdx.y * 128, n0 = blockIdx.x * 128;
    const int tid = threadIdx.x;                  // 256
    const int wid = tid >> 5;
    const int wm = (wid >> 2) * 64, wn = (wid & 3) * 32;
    wmma::fragment<wmma::accumulator, 16, 16, 16, float> acc[4][2];
#pragma unroll
    for (int i = 0; i < 4; i++)
#pragma unroll
        for (int j = 0; j < 2; j++) wmma::fill_fragment(acc[i][j], 0.f);
    const int r = tid >> 1;
    const int c = (tid & 1) * 8;
    for (int k0 = 0; k0 < D_; k0 += 16) {
        *reinterpret_cast<uint4*>(&As[r * 16 + c]) =
            *reinterpret_cast<const uint4*>(&g_outs_bf[(size_t)(m0 + r) * D_ + k0 + c]);
        *reinterpret_cast<uint4*>(&Bs[r * 16 + c]) =
            *reinterpret_cast<const uint4*>(&g_wlin_bf[(size_t)(n0 + r) * D_ + k0 + c]);
        __syncthreads();
        wmma::fragment<wmma::matrix_b, 16, 16, 16, __nv_bfloat16, wmma::col_major> bf[2];
#pragma unroll
        for (int j = 0; j < 2; j++)
            wmma::load_matrix_sync(bf[j], &Bs[(wn + j * 16) * 16], 16);
#pragma unroll
        for (int i = 0; i < 4; i++) {
            wmma::fragment<wmma::matrix_a, 16, 16, 16, __nv_bfloat16, wmma::row_major> af;
            wmma::load_matrix_sync(af, &As[(wm + i * 16) * 16], 16);
#pragma unroll
            for (int j = 0; j < 2; j++) wmma::mma_sync(acc[i][j], af, bf[j], acc[i][j]);
        }
        __syncthreads();
    }
#pragma unroll
    for (int i = 0; i < 4; i++)
#pragma unroll
        for (int j = 0; j < 2; j++)
            wmma::store_matrix_sync(C + (size_t)(m0 + wm + i * 16) * V_ + n0 + wn + j * 16,
                                    acc[i][j], V_, wmma::mem_row_major);
}

// ---------------- log_softmax (adds b_lin, in-place over d_out rows) --------
__global__ void k_logsoftmax(float* __restrict__ logits, const float* __restrict__ b_lin) {
    const int row = blockIdx.x;
    float* p = logits + (size_t)row * V_;
    const int tid = threadIdx.x;
    float m = -1e30f, s = 0.f;
    for (int v = tid; v < V_; v += 256) {
        float x = p[v] + b_lin[v];
        if (x > m) { s = s * __expf(m - x) + 1.f; m = x; }
        else       { s += __expf(x - m); }
    }
    __shared__ float sm[256], ss[256];
    sm[tid] = m; ss[tid] = s;
    __syncthreads();
    for (int off = 128; off; off >>= 1) {
        if (tid < off) {
            float m2 = sm[tid + off], s2 = ss[tid + off];
            float M = fmaxf(sm[tid], m2);
            ss[tid] = ss[tid] * __expf(sm[tid] - M) + s2 * __expf(m2 - M);
            sm[tid] = M;
        }
        __syncthreads();
    }
    float lse = sm[0] + logf(ss[0]);
    for (int v = tid; v < V_; v += 256)
        p[v] = p[v] + b_lin[v] - lse;
}

// ---------------- host driver ----------------------------------------------
extern "C" void kernel_launch(void* const* d_in, const int* in_sizes, int n_in,
                              void* d_out, int out_size) {
    const int*   tokens     = (const int*)d_in[0];
    const float* h0         = (const float*)d_in[1];
    const float* c0         = (const float*)d_in[2];
    const float* context    = (const float*)d_in[3];
    const float* embedding  = (const float*)d_in[4];
    const float* Wih        = (const float*)d_in[5];
    const float* Whh        = (const float*)d_in[6];
    const float* bih        = (const float*)d_in[7];
    const float* bhh        = (const float*)d_in[8];
    const float* W_attn_in  = (const float*)d_in[9];
    const float* W_attn_out = (const float*)d_in[10];
    const float* W_lin      = (const float*)d_in[11];
    const float* b_lin      = (const float*)d_in[12];
    float* out = (float*)d_out;

    cudaFuncSetAttribute(k_scan, cudaFuncAttributeMaxDynamicSharedMemorySize, SMEM_BYTES);

    const float* Wih1 = Wih + (size_t)G4_ * D_;
    const float* Whh1 = Whh + (size_t)G4_ * H_;

    k_reset<<<1, 1>>>();
    k_convert_wlin<<<(V_ * D_ / 4 + 255) / 256, 256>>>(W_lin);
    k_gemm_pre<<<dim3(G4_ / 64, MR_ / 64), 256>>>(tokens, embedding, Wih, bih, bhh);
    k_c2<<<dim3(H_ / 64, (B_ * S_) / 64), 256>>>(context, W_attn_in);
    k_scan<<<CTAS_, 256, SMEM_BYTES>>>(Whh, Wih1, Whh1, bih, bhh, context,
                                       W_attn_out, h0, c0, out);
    k_wmma<<<dim3(V_ / 128, MR_ / 128), 256>>>(out);
    k_logsoftmax<<<MR_, 256>>>(out, b_lin);
}

// round 8
// speedup vs baseline: 9.2926x; 1.1163x over previous
#include <cuda_runtime.h>
#include <cuda_bf16.h>
#include <mma.h>
using namespace nvcuda;

#define B_  32
#define T_  64
#define S_  64
#define H_  512
#define D_  512
#define V_  32000
#define G4_ 2048            // 4*H
#define MR_ 2048            // T*B rows

#define CTAS_ 128
#define UPC_  4             // units per CTA (both layers)

// d_out layout (f32): log_probs [T,B,V], hT [2,B,H], cT [2,B,H], attn [B,S]
#define OFF_HT   ((size_t)T_ * B_ * V_)
#define OFF_CT   (OFF_HT + (size_t)2 * B_ * H_)
#define OFF_ATTN (OFF_CT + (size_t)2 * B_ * H_)

// ---------------- device scratch -------------------------------------------
__device__ float g_pre0[(size_t)T_ * G4_ * B_];       // [t][gate_row][b]  16MB
__device__ float g_c2[(size_t)B_ * S_ * H_];          // context @ W_attn_in 4MB
__device__ float g_h0[2][B_ * H_];                    // h layer0, [b][k] row-major
__device__ float g_h1[2][B_ * H_];                    // h layer1, [b][k] row-major
__device__ float4 g_cat4[(2 * H_ / 4) * B_];          // [ctx ; h1] k4 layout
__device__ __nv_bfloat16 g_outs_bf[(size_t)MR_ * H_];
__device__ __nv_bfloat16 g_wlin_bf[(size_t)V_ * D_];
__device__ unsigned g_bar;

__device__ __forceinline__ float sigf(float x) { return 1.f / (1.f + __expf(-x)); }

__global__ void k_reset() { g_bar = 0u; }

// ---------------- W_lin fp32 -> bf16 ---------------------------------------
__global__ void k_convert_wlin(const float* __restrict__ w) {
    int i = blockIdx.x * blockDim.x + threadIdx.x;
    if (i < (V_ * D_) / 4) {
        float4 v = reinterpret_cast<const float4*>(w)[i];
        __nv_bfloat162* o = reinterpret_cast<__nv_bfloat162*>(g_wlin_bf);
        o[i * 2]     = __floats2bfloat162_rn(v.x, v.y);
        o[i * 2 + 1] = __floats2bfloat162_rn(v.z, v.w);
    }
}

// ---------------- embed + input projection: pre0 = emb @ Wih0^T + b --------
// stored as g_pre0[t][n][b]
__global__ void k_gemm_pre(const int* __restrict__ tokens,
                           const float* __restrict__ embedding,
                           const float* __restrict__ Wih0,
                           const float* __restrict__ bih0,
                           const float* __restrict__ bhh0) {
    __shared__ float As[64][33];
    __shared__ float Bs[64][33];
    __shared__ int  toks[64];
    const int tid = threadIdx.x;                 // 256 threads
    const int m0 = blockIdx.y * 64, n0 = blockIdx.x * 64;
    if (tid < 64) {
        int m = m0 + tid;
        int t = m >> 5, b = m & 31;
        toks[tid] = tokens[b * T_ + t];
    }
    __syncthreads();
    float acc[4][4] = {};
    const int ty = tid / 16, tx = tid % 16;
    for (int k0 = 0; k0 < D_; k0 += 32) {
#pragma unroll
        for (int it = 0; it < 2; it++) {
            int idx = tid + it * 256;            // 512 float4 slots (64 rows x 8)
            int r = idx >> 3;
            int c = (idx & 7) * 4;
            float4 va = *reinterpret_cast<const float4*>(
                embedding + (size_t)toks[r] * D_ + k0 + c);
            As[r][c] = va.x; As[r][c + 1] = va.y; As[r][c + 2] = va.z; As[r][c + 3] = va.w;
            float4 vb = *reinterpret_cast<const float4*>(
                Wih0 + (size_t)(n0 + r) * D_ + k0 + c);
            Bs[r][c] = vb.x; Bs[r][c + 1] = vb.y; Bs[r][c + 2] = vb.z; Bs[r][c + 3] = vb.w;
        }
        __syncthreads();
#pragma unroll
        for (int kk = 0; kk < 32; kk++) {
            float a[4], b4[4];
#pragma unroll
            for (int i = 0; i < 4; i++) a[i]  = As[ty * 4 + i][kk];
#pragma unroll
            for (int j = 0; j < 4; j++) b4[j] = Bs[tx * 4 + j][kk];
#pragma unroll
            for (int i = 0; i < 4; i++)
#pragma unroll
                for (int j = 0; j < 4; j++) acc[i][j] += a[i] * b4[j];
        }
        __syncthreads();
    }
#pragma unroll
    for (int i = 0; i < 4; i++)
#pragma unroll
        for (int j = 0; j < 4; j++) {
            int m = m0 + ty * 4 + i, n = n0 + tx * 4 + j;
            int t = m >> 5, b = m & 31;
            g_pre0[((size_t)t * G4_ + n) * B_ + b] = acc[i][j] + bih0[n] + bhh0[n];
        }
}

// ---------------- C2 = context @ W_attn_in  (A[2048,512] @ B[512,512]) ------
__global__ void k_c2(const float* __restrict__ A, const float* __restrict__ Wq) {
    __shared__ float As[64][65];
    __shared__ float Bs[64][65];
    const int tid = threadIdx.x;
    const int m0 = blockIdx.y * 64, n0 = blockIdx.x * 64;
    float acc[4][4] = {};
    const int ty = tid / 16, tx = tid % 16;
    for (int k0 = 0; k0 < H_; k0 += 64) {
#pragma unroll
        for (int it = 0; it < 4; it++) {
            int idx = tid + it * 256;            // 1024 float4 slots (64 x 16)
            int r = idx >> 4;
            int c = (idx & 15) * 4;
            float4 va = *reinterpret_cast<const float4*>(
                A + (size_t)(m0 + r) * H_ + k0 + c);
            As[r][c] = va.x; As[r][c + 1] = va.y; As[r][c + 2] = va.z; As[r][c + 3] = va.w;
            float4 vb = *reinterpret_cast<const float4*>(
                Wq + (size_t)(k0 + r) * H_ + n0 + c);
            Bs[r][c] = vb.x; Bs[r][c + 1] = vb.y; Bs[r][c + 2] = vb.z; Bs[r][c + 3] = vb.w;
        }
        __syncthreads();
#pragma unroll
        for (int kk = 0; kk < 64; kk++) {
            float a[4], b4[4];
#pragma unroll
            for (int i = 0; i < 4; i++) a[i]  = As[ty * 4 + i][kk];
#pragma unroll
            for (int j = 0; j < 4; j++) b4[j] = Bs[kk][tx * 4 + j];
#pragma unroll
            for (int i = 0; i < 4; i++)
#pragma unroll
                for (int j = 0; j < 4; j++) acc[i][j] += a[i] * b4[j];
        }
        __syncthreads();
    }
#pragma unroll
    for (int i = 0; i < 4; i++)
#pragma unroll
        for (int j = 0; j < 4; j++)
            g_c2[(size_t)(m0 + ty * 4 + i) * H_ + n0 + tx * 4 + j] = acc[i][j];
}

// ---------------- persistent scan kernel (tf32 WMMA for L0/L1) --------------
// SMEM float offsets
#define SM_W0    0                          // 16 x 520
#define SM_W1    8320                       // 16 x 1040
#define SM_WOS   24960                      // 4 x 1024
#define SM_STAGE 29056                      // 32 x 520 (also k4 cat region 16384)
#define SM_PBUF  45696                      // 8 x 256 wmma partials
#define SM_GBUF  47744                      // 16 x 32
#define SM_CB    48256                      // 2 x 4 x 32
#define SM_B1    48512                      // 16
#define SM_PART  48528                      // 8 x 32
#define SMEM_FLOATS 48784
#define SMEM_BYTES  (SMEM_FLOATS * 4)

#define LDW0  520
#define LDW1  1040
#define LDST  520

__device__ __forceinline__ void gridbar(unsigned target) {
    __threadfence();
    __syncthreads();
    if (threadIdx.x == 0) {
        atomicAdd(&g_bar, 1u);
        volatile unsigned* vb = &g_bar;
        while (*vb < target) { }
    }
    __syncthreads();
}

// copy 32x512 row-major h (float4 linear, 4096 f4) into padded stage [b][520]
__device__ __forceinline__ void stage_rows(float* stg, const float4* src, int tid) {
    for (int idx = tid; idx < 4096; idx += 256) {
        int b = idx >> 7, j = idx & 127;
        reinterpret_cast<float4*>(stg + b * LDST)[j] = __ldcg(&src[idx]);
    }
}

__global__ void __launch_bounds__(256, 1)
k_scan(const float* __restrict__ Whh0, const float* __restrict__ Wih1,
       const float* __restrict__ Whh1, const float* __restrict__ bih,
       const float* __restrict__ bhh, const float* __restrict__ context,
       const float* __restrict__ Wout, const float* __restrict__ h0in,
       const float* __restrict__ c0in, float* __restrict__ out) {
    extern __shared__ float sm[];
    float*  W0s   = sm + SM_W0;
    float*  W1s   = sm + SM_W1;
    float*  Wos   = sm + SM_WOS;
    float*  stg   = sm + SM_STAGE;
    float4* stage4 = reinterpret_cast<float4*>(sm + SM_STAGE);   // k4 view (attn-out)
    float*  pbuf  = sm + SM_PBUF;
    float*  gbuf  = sm + SM_GBUF;
    float*  cb    = sm + SM_CB;
    float*  bias1 = sm + SM_B1;
    float*  part  = sm + SM_PART;

    const int cta = blockIdx.x;
    const int tid = threadIdx.x;
    const int w   = tid >> 5;
    const int lane = tid & 31;
    const int u0  = cta * UPC_;
    const int wn  = w & 1;            // n-tile (batch 16s)
    const int wkc = w >> 1;           // k-chunk (128s)

    // -------- prologue: weights -> SMEM -----------------------------------
    // W0s rows r = gate*4+ul : Whh0[(gate*512 + u0+ul)][:], padded ld 520
    for (int idx = tid; idx < 16 * 128; idx += 256) {
        int r = idx >> 7, kq = idx & 127;
        int row = ((r >> 2) * H_) + u0 + (r & 3);
        reinterpret_cast<float4*>(W0s + r * LDW0)[kq] =
            *reinterpret_cast<const float4*>(Whh0 + (size_t)row * H_ + kq * 4);
    }
    // W1s rows r: [Wih1 row (512) | Whh1 row (512)], padded ld 1040
    for (int idx = tid; idx < 16 * 256; idx += 256) {
        int r = idx >> 8, kq = idx & 255;
        int row = ((r >> 2) * H_) + u0 + (r & 3);
        const float* src = (kq < 128)
            ? (Wih1 + (size_t)row * H_ + kq * 4)
            : (Whh1 + (size_t)row * H_ + (kq - 128) * 4);
        reinterpret_cast<float4*>(W1s + r * LDW1)[kq] =
            *reinterpret_cast<const float4*>(src);
    }
    // Wos rows r: W_attn_out[u0+r][0..1023]
    for (int idx = tid; idx < 4 * 256; idx += 256) {
        int r = idx >> 8, kq = idx & 255;
        reinterpret_cast<float4*>(Wos + r * 1024)[kq] =
            *reinterpret_cast<const float4*>(Wout + (size_t)(u0 + r) * (2 * H_) + kq * 4);
    }
    if (tid < 16) {
        int row = ((tid >> 2) * H_) + u0 + (tid & 3);
        bias1[tid] = bih[G4_ + row] + bhh[G4_ + row];
    }
    {   // cell state: cb[l*128 + ul*32 + b]
        int l = tid >> 7, ul = (tid >> 5) & 3, b = tid & 31;
        cb[tid] = c0in[(size_t)l * B_ * H_ + (size_t)b * H_ + u0 + ul];
    }
    if (tid < 32) {   // initial h -> row-major global
        int b = tid;
#pragma unroll
        for (int ul = 0; ul < 4; ul++) {
            __stcg(&g_h0[0][b * H_ + u0 + ul], h0in[(size_t)b * H_ + u0 + ul]);
            __stcg(&g_h1[0][b * H_ + u0 + ul], h0in[(size_t)B_ * H_ + b * H_ + u0 + ul]);
        }
    }
    unsigned nbar = 0;
    gridbar(++nbar * CTAS_);

    // -------- main scan ----------------------------------------------------
    for (int t = 0; t < T_; t++) {
        const int p = t & 1;

        // ===== layer 0: gates = W0 (16x512) x h0^T (512x32), tf32 wmma =====
        stage_rows(stg, reinterpret_cast<const float4*>(g_h0[p]), tid);
        __syncthreads();
        {
            wmma::fragment<wmma::accumulator, 16, 16, 8, float> c;
            wmma::fill_fragment(c, 0.f);
#pragma unroll
            for (int kk = 0; kk < 16; kk++) {
                int k = wkc * 128 + kk * 8;
                wmma::fragment<wmma::matrix_a, 16, 16, 8, wmma::precision::tf32, wmma::row_major> a;
                wmma::fragment<wmma::matrix_b, 16, 16, 8, wmma::precision::tf32, wmma::col_major> b;
                wmma::load_matrix_sync(a, W0s + k, LDW0);
                wmma::load_matrix_sync(b, stg + (wn * 16) * LDST + k, LDST);
#pragma unroll
                for (int i = 0; i < a.num_elements; i++) a.x[i] = wmma::__float_to_tf32(a.x[i]);
#pragma unroll
                for (int i = 0; i < b.num_elements; i++) b.x[i] = wmma::__float_to_tf32(b.x[i]);
                wmma::mma_sync(c, a, b, c);
            }
            wmma::store_matrix_sync(pbuf + w * 256, c, 16, wmma::mem_row_major);
        }
        __syncthreads();
        for (int o = tid; o < 512; o += 256) {          // reduce 4 k-chunks
            int r = o >> 5, b = o & 31;
            float s = 0.f;
#pragma unroll
            for (int kc = 0; kc < 4; kc++)
                s += pbuf[((b >> 4) + 2 * kc) * 256 + r * 16 + (b & 15)];
            gbuf[r * 32 + b] = s;
        }
        __syncthreads();
        if (tid < 128) {
            int ul = tid >> 5, b = tid & 31, u = u0 + ul;
            const float* pre = g_pre0 + (size_t)t * G4_ * B_;
            float gi = sigf(gbuf[(0  + ul) * 32 + b] + __ldg(&pre[((size_t)0 * H_ + u) * B_ + b]));
            float gf = sigf(gbuf[(4  + ul) * 32 + b] + __ldg(&pre[((size_t)1 * H_ + u) * B_ + b]));
            float gg = tanhf(gbuf[(8  + ul) * 32 + b] + __ldg(&pre[((size_t)2 * H_ + u) * B_ + b]));
            float go = sigf(gbuf[(12 + ul) * 32 + b] + __ldg(&pre[((size_t)3 * H_ + u) * B_ + b]));
            float c = gf * cb[ul * 32 + b] + gi * gg;
            cb[ul * 32 + b] = c;
            float h = go * tanhf(c);
            __stcg(&g_h0[p ^ 1][b * H_ + u], h);
            if (t == T_ - 1) {
                out[OFF_HT + (size_t)b * H_ + u] = h;
                out[OFF_CT + (size_t)b * H_ + u] = c;
            }
        }
        gridbar(++nbar * CTAS_);

        // ===== layer 1: two K passes (x = h0new, then h1old), tf32 wmma =====
        {
            wmma::fragment<wmma::accumulator, 16, 16, 8, float> c;
            wmma::fill_fragment(c, 0.f);
#pragma unroll
            for (int pass = 0; pass < 2; pass++) {
                const float4* src = pass ? reinterpret_cast<const float4*>(g_h1[p])
                                         : reinterpret_cast<const float4*>(g_h0[p ^ 1]);
                stage_rows(stg, src, tid);
                __syncthreads();
                const int koff = pass * 512;
#pragma unroll
                for (int kk = 0; kk < 16; kk++) {
                    int k = wkc * 128 + kk * 8;
                    wmma::fragment<wmma::matrix_a, 16, 16, 8, wmma::precision::tf32, wmma::row_major> a;
                    wmma::fragment<wmma::matrix_b, 16, 16, 8, wmma::precision::tf32, wmma::col_major> b;
                    wmma::load_matrix_sync(a, W1s + koff + k, LDW1);
                    wmma::load_matrix_sync(b, stg + (wn * 16) * LDST + k, LDST);
#pragma unroll
                    for (int i = 0; i < a.num_elements; i++) a.x[i] = wmma::__float_to_tf32(a.x[i]);
#pragma unroll
                    for (int i = 0; i < b.num_elements; i++) b.x[i] = wmma::__float_to_tf32(b.x[i]);
                    wmma::mma_sync(c, a, b, c);
                }
                __syncthreads();   // stage reuse between passes
            }
            wmma::store_matrix_sync(pbuf + w * 256, c, 16, wmma::mem_row_major);
        }
        __syncthreads();
        for (int o = tid; o < 512; o += 256) {
            int r = o >> 5, b = o & 31;
            float s = 0.f;
#pragma unroll
            for (int kc = 0; kc < 4; kc++)
                s += pbuf[((b >> 4) + 2 * kc) * 256 + r * 16 + (b & 15)];
            gbuf[r * 32 + b] = s;
        }
        __syncthreads();
        if (tid < 128) {
            int ul = tid >> 5, b = tid & 31, u = u0 + ul;
            float gi = sigf(gbuf[(0  + ul) * 32 + b] + bias1[0  + ul]);
            float gf = sigf(gbuf[(4  + ul) * 32 + b] + bias1[4  + ul]);
            float gg = tanhf(gbuf[(8  + ul) * 32 + b] + bias1[8  + ul]);
            float go = sigf(gbuf[(12 + ul) * 32 + b] + bias1[12 + ul]);
            float c = gf * cb[128 + ul * 32 + b] + gi * gg;
            cb[128 + ul * 32 + b] = c;
            float h = go * tanhf(c);
            __stcg(&g_h1[p ^ 1][b * H_ + u], h);
            if (t == T_ - 1) {
                out[OFF_HT + (size_t)B_ * H_ + (size_t)b * H_ + u] = h;
                out[OFF_CT + (size_t)B_ * H_ + (size_t)b * H_ + u] = c;
            }
        }
        gridbar(++nbar * CTAS_);

        // ===== attention (CTAs 0..31, one batch element each) =====
        if (cta < B_) {
            float* qs  = stg;                  // 512
            float* sc  = qs + 512;             // 64
            float* att = sc + 64;              // 64
            const float4* h1row = reinterpret_cast<const float4*>(g_h1[p ^ 1] + cta * H_);
            for (int q = tid; q < 128; q += 256)
                reinterpret_cast<float4*>(qs)[q] = __ldcg(&h1row[q]);
            __syncthreads();
            for (int s = w; s < S_; s += 8) {
                const float* c2 = g_c2 + (size_t)(cta * S_ + s) * H_;
                float a = 0.f;
                for (int k = lane; k < H_; k += 32) a += c2[k] * qs[k];
#pragma unroll
                for (int off = 16; off; off >>= 1) a += __shfl_xor_sync(0xffffffffu, a, off);
                if (lane == 0) sc[s] = a;
            }
            __syncthreads();
            if (tid < 32) {
                float v0 = sc[tid], v1 = sc[tid + 32];
                float m = fmaxf(v0, v1);
#pragma unroll
                for (int off = 16; off; off >>= 1) m = fmaxf(m, __shfl_xor_sync(0xffffffffu, m, off));
                float e0 = __expf(v0 - m), e1 = __expf(v1 - m);
                float s2 = e0 + e1;
#pragma unroll
                for (int off = 16; off; off >>= 1) s2 += __shfl_xor_sync(0xffffffffu, s2, off);
                float inv = 1.f / s2;
                att[tid] = e0 * inv; att[tid + 32] = e1 * inv;
                if (t == T_ - 1) {
                    out[OFF_ATTN + cta * S_ + tid]      = e0 * inv;
                    out[OFF_ATTN + cta * S_ + tid + 32] = e1 * inv;
                }
            }
            __syncthreads();
            for (int h = tid; h < H_; h += 256) {
                float a = 0.f;
                const float* cx = context + (size_t)cta * S_ * H_ + h;
#pragma unroll 8
                for (int s = 0; s < S_; s++) a += att[s] * cx[(size_t)s * H_];
                __stcg(&reinterpret_cast<float*>(g_cat4)[((h >> 2) * 32 + cta) * 4 + (h & 3)], a);
                int h2 = H_ + h;
                __stcg(&reinterpret_cast<float*>(g_cat4)[((h2 >> 2) * 32 + cta) * 4 + (h2 & 3)], qs[h]);
            }
        }
        gridbar(++nbar * CTAS_);

        // ===== attention-out (scalar, k4 stage): warp = (row=w&3, sub=w>>2) =====
        {
            float oa = 0.f, ob = 0.f;
            const int row = w & 3, sub = w >> 2;
            for (int half = 0; half < 2; half++) {
                for (int i = tid; i < 4096; i += 256)
                    stage4[i] = __ldcg(&g_cat4[half * 4096 + i]);
                __syncthreads();
                const float4* wr = reinterpret_cast<const float4*>(Wos + row * 1024 + half * H_);
                const int i0 = sub * 64;
#pragma unroll 4
                for (int i = 0; i < 64; i++) {
                    float4 h = stage4[(i0 + i) * 32 + lane];
                    float4 x = wr[i0 + i];
                    oa += x.x * h.x + x.y * h.y;
                    ob += x.z * h.z + x.w * h.w;
                }
                __syncthreads();
            }
            part[w * 32 + lane] = oa + ob;
        }
        __syncthreads();
        if (tid < 128) {
            int r = tid >> 5, b = tid & 31;
            float v = tanhf(part[r * 32 + b] + part[(r + 4) * 32 + b]);
            g_outs_bf[((size_t)t * B_ + b) * H_ + u0 + r] = __float2bfloat16(v);
        }
        __syncthreads();   // protect stage before next step's restage
    }
}

// ---------------- vocab GEMM: logits = outs_bf @ wlin_bf^T ------------------
__global__ void k_wmma(float* __restrict__ C) {
    __shared__ __align__(16) __nv_bfloat16 As[128 * 16];
    __shared__ __align__(16) __nv_bfloat16 Bs[128 * 16];
    const int m0 = blockIdx.y * 128, n0 = blockIdx.x * 128;
    const int tid = threadIdx.x;                  // 256
    const int wid = tid >> 5;
    const int wm = (wid >> 2) * 64, wn = (wid & 3) * 32;
    wmma::fragment<wmma::accumulator, 16, 16, 16, float> acc[4][2];
#pragma unroll
    for (int i = 0; i < 4; i++)
#pragma unroll
        for (int j = 0; j < 2; j++) wmma::fill_fragment(acc[i][j], 0.f);
    const int r = tid >> 1;
    const int c = (tid & 1) * 8;
    for (int k0 = 0; k0 < D_; k0 += 16) {
        *reinterpret_cast<uint4*>(&As[r * 16 + c]) =
            *reinterpret_cast<const uint4*>(&g_outs_bf[(size_t)(m0 + r) * D_ + k0 + c]);
        *reinterpret_cast<uint4*>(&Bs[r * 16 + c]) =
            *reinterpret_cast<const uint4*>(&g_wlin_bf[(size_t)(n0 + r) * D_ + k0 + c]);
        __syncthreads();
        wmma::fragment<wmma::matrix_b, 16, 16, 16, __nv_bfloat16, wmma::col_major> bf[2];
#pragma unroll
        for (int j = 0; j < 2; j++)
            wmma::load_matrix_sync(bf[j], &Bs[(wn + j * 16) * 16], 16);
#pragma unroll
        for (int i = 0; i < 4; i++) {
            wmma::fragment<wmma::matrix_a, 16, 16, 16, __nv_bfloat16, wmma::row_major> af;
            wmma::load_matrix_sync(af, &As[(wm + i * 16) * 16], 16);
#pragma unroll
            for (int j = 0; j < 2; j++) wmma::mma_sync(acc[i][j], af, bf[j], acc[i][j]);
        }
        __syncthreads();
    }
#pragma unroll
    for (int i = 0; i < 4; i++)
#pragma unroll
        for (int j = 0; j < 2; j++)
            wmma::store_matrix_sync(C + (size_t)(m0 + wm + i * 16) * V_ + n0 + wn + j * 16,
                                    acc[i][j], V_, wmma::mem_row_major);
}

// ---------------- log_softmax (adds b_lin, in-place over d_out rows) --------
__global__ void k_logsoftmax(float* __restrict__ logits, const float* __restrict__ b_lin) {
    const int row = blockIdx.x;
    float* p = logits + (size_t)row * V_;
    const int tid = threadIdx.x;
    float m = -1e30f, s = 0.f;
    for (int v = tid; v < V_; v += 256) {
        float x = p[v] + b_lin[v];
        if (x > m) { s = s * __expf(m - x) + 1.f; m = x; }
        else       { s += __expf(x - m); }
    }
    __shared__ float sm[256], ss[256];
    sm[tid] = m; ss[tid] = s;
    __syncthreads();
    for (int off = 128; off; off >>= 1) {
        if (tid < off) {
            float m2 = sm[tid + off], s2 = ss[tid + off];
            float M = fmaxf(sm[tid], m2);
            ss[tid] = ss[tid] * __expf(sm[tid] - M) + s2 * __expf(m2 - M);
            sm[tid] = M;
        }
        __syncthreads();
    }
    float lse = sm[0] + logf(ss[0]);
    for (int v = tid; v < V_; v += 256)
        p[v] = p[v] + b_lin[v] - lse;
}

// ---------------- host driver ----------------------------------------------
extern "C" void kernel_launch(void* const* d_in, const int* in_sizes, int n_in,
                              void* d_out, int out_size) {
    const int*   tokens     = (const int*)d_in[0];
    const float* h0         = (const float*)d_in[1];
    const float* c0         = (const float*)d_in[2];
    const float* context    = (const float*)d_in[3];
    const float* embedding  = (const float*)d_in[4];
    const float* Wih        = (const float*)d_in[5];
    const float* Whh        = (const float*)d_in[6];
    const float* bih        = (const float*)d_in[7];
    const float* bhh        = (const float*)d_in[8];
    const float* W_attn_in  = (const float*)d_in[9];
    const float* W_attn_out = (const float*)d_in[10];
    const float* W_lin      = (const float*)d_in[11];
    const float* b_lin      = (const float*)d_in[12];
    float* out = (float*)d_out;

    cudaFuncSetAttribute(k_scan, cudaFuncAttributeMaxDynamicSharedMemorySize, SMEM_BYTES);

    const float* Wih1 = Wih + (size_t)G4_ * D_;
    const float* Whh1 = Whh + (size_t)G4_ * H_;

    k_reset<<<1, 1>>>();
    k_convert_wlin<<<(V_ * D_ / 4 + 255) / 256, 256>>>(W_lin);
    k_gemm_pre<<<dim3(G4_ / 64, MR_ / 64), 256>>>(tokens, embedding, Wih, bih, bhh);
    k_c2<<<dim3(H_ / 64, (B_ * S_) / 64), 256>>>(context, W_attn_in);
    k_scan<<<CTAS_, 256, SMEM_BYTES>>>(Whh, Wih1, Whh1, bih, bhh, context,
                                       W_attn_out, h0, c0, out);
    k_wmma<<<dim3(V_ / 128, MR_ / 128), 256>>>(out);
    k_logsoftmax<<<MR_, 256>>>(out, b_lin);
}

// round 9
// speedup vs baseline: 9.5774x; 1.0306x over previous
#include <cuda_runtime.h>
#include <cuda_bf16.h>
#include <mma.h>
using namespace nvcuda;

#define B_  32
#define T_  64
#define S_  64
#define H_  512
#define D_  512
#define V_  32000
#define G4_ 2048            // 4*H
#define MR_ 2048            // T*B rows

#define CTAS_ 128
#define UPC_  4             // units per CTA (both layers)

// d_out layout (f32): log_probs [T,B,V], hT [2,B,H], cT [2,B,H], attn [B,S]
#define OFF_HT   ((size_t)T_ * B_ * V_)
#define OFF_CT   (OFF_HT + (size_t)2 * B_ * H_)
#define OFF_ATTN (OFF_CT + (size_t)2 * B_ * H_)

// ---------------- device scratch -------------------------------------------
__device__ float g_pre0[(size_t)T_ * G4_ * B_];       // [t][gate_row][b]  16MB
__device__ float g_c2[(size_t)B_ * S_ * H_];          // context @ W_attn_in 4MB
__device__ float g_h0[2][B_ * H_];                    // h layer0, [b][k] row-major
__device__ float g_h1[2][B_ * H_];                    // h layer1, [b][k] row-major
__device__ float4 g_cat4[(2 * H_ / 4) * B_];          // [ctx ; h1] k4 layout
__device__ __nv_bfloat16 g_outs_bf[(size_t)MR_ * H_];
__device__ __nv_bfloat16 g_wlin_bf[(size_t)V_ * D_];
__device__ unsigned g_bar;

__device__ __forceinline__ float sigf(float x) { return 1.f / (1.f + __expf(-x)); }
__device__ __forceinline__ float totf(float x) { return wmma::__float_to_tf32(x); }

__global__ void k_reset() { g_bar = 0u; }

// ---------------- W_lin fp32 -> bf16 ---------------------------------------
__global__ void k_convert_wlin(const float* __restrict__ w) {
    int i = blockIdx.x * blockDim.x + threadIdx.x;
    if (i < (V_ * D_) / 4) {
        float4 v = reinterpret_cast<const float4*>(w)[i];
        __nv_bfloat162* o = reinterpret_cast<__nv_bfloat162*>(g_wlin_bf);
        o[i * 2]     = __floats2bfloat162_rn(v.x, v.y);
        o[i * 2 + 1] = __floats2bfloat162_rn(v.z, v.w);
    }
}

// ---------------- embed + input projection (tf32 WMMA) ----------------------
// pre0[t][n][b] = sum_k emb[tok(t,b)][k] * Wih0[n][k] + bih0[n] + bhh0[n]
// tile m128 x n128 x k32; 8 warps (2m x 4n), warp tile 64x32
__global__ void __launch_bounds__(256)
k_gemm_pre(const int* __restrict__ tokens,
           const float* __restrict__ embedding,
           const float* __restrict__ Wih0,
           const float* __restrict__ bih0,
           const float* __restrict__ bhh0) {
    __shared__ float As[128 * 36];
    __shared__ float Bs[128 * 36];
    __shared__ float scr[8 * 320];        // per-warp 16x16 frag scratch, ldm 20
    __shared__ float bsh[128];
    __shared__ int   toks[128];
    const int tid = threadIdx.x;
    const int w   = tid >> 5;
    const int lane = tid & 31;
    const int m0 = blockIdx.y * 128, n0 = blockIdx.x * 128;
    const int wm = (w >> 2) * 64, wn = (w & 3) * 32;

    if (tid < 128) {
        int m = m0 + tid;
        toks[tid] = tokens[(m & 31) * T_ + (m >> 5)];
        bsh[tid] = bih0[n0 + tid] + bhh0[n0 + tid];
    }
    __syncthreads();

    wmma::fragment<wmma::accumulator, 16, 16, 8, float> acc[4][2];
#pragma unroll
    for (int i = 0; i < 4; i++)
#pragma unroll
        for (int j = 0; j < 2; j++) wmma::fill_fragment(acc[i][j], 0.f);

    for (int k0 = 0; k0 < D_; k0 += 32) {
#pragma unroll
        for (int it = 0; it < 4; it++) {
            int idx = tid + it * 256;        // 1024 f4 slots: 128 rows x 8 f4
            int r = idx >> 3, c = (idx & 7) * 4;
            float4 va = *reinterpret_cast<const float4*>(
                embedding + (size_t)toks[r] * D_ + k0 + c);
            As[r * 36 + c] = totf(va.x); As[r * 36 + c + 1] = totf(va.y);
            As[r * 36 + c + 2] = totf(va.z); As[r * 36 + c + 3] = totf(va.w);
            float4 vb = *reinterpret_cast<const float4*>(
                Wih0 + (size_t)(n0 + r) * D_ + k0 + c);
            Bs[r * 36 + c] = totf(vb.x); Bs[r * 36 + c + 1] = totf(vb.y);
            Bs[r * 36 + c + 2] = totf(vb.z); Bs[r * 36 + c + 3] = totf(vb.w);
        }
        __syncthreads();
#pragma unroll
        for (int kk = 0; kk < 4; kk++) {
            wmma::fragment<wmma::matrix_b, 16, 16, 8, wmma::precision::tf32, wmma::col_major> b[2];
#pragma unroll
            for (int j = 0; j < 2; j++)
                wmma::load_matrix_sync(b[j], Bs + (wn + j * 16) * 36 + kk * 8, 36);
#pragma unroll
            for (int i = 0; i < 4; i++) {
                wmma::fragment<wmma::matrix_a, 16, 16, 8, wmma::precision::tf32, wmma::row_major> a;
                wmma::load_matrix_sync(a, As + (wm + i * 16) * 36 + kk * 8, 36);
#pragma unroll
                for (int j = 0; j < 2; j++) wmma::mma_sync(acc[i][j], a, b[j], acc[i][j]);
            }
        }
        __syncthreads();
    }
    // epilogue: frag -> scratch -> scattered (coalesced-in-b) global writes
#pragma unroll
    for (int i = 0; i < 4; i++)
#pragma unroll
        for (int j = 0; j < 2; j++) {
            wmma::store_matrix_sync(scr + w * 320, acc[i][j], 20, wmma::mem_row_major);
            __syncwarp();
            int c = lane >> 1;                    // 0..15 (n within frag)
            int r0 = (lane & 1) * 8;              // 0 or 8
            int n = n0 + wn + j * 16 + c;
            int mbase = m0 + wm + i * 16 + r0;
            int t = mbase >> 5, b0 = mbase & 31;
            float bias = bsh[wn + j * 16 + c];
            float* dst = g_pre0 + ((size_t)t * G4_ + n) * B_ + b0;
#pragma unroll
            for (int rr = 0; rr < 8; rr++)
                dst[rr] = scr[w * 320 + (r0 + rr) * 20 + c] + bias;
            __syncwarp();
        }
}

// ---------------- C2 = context @ W_attn_in (tf32 WMMA) ----------------------
// C2[m][n] = sum_k A[m][k] * Wq[k][n]; tile m128 x n128 x k32
__global__ void __launch_bounds__(256)
k_c2(const float* __restrict__ A, const float* __restrict__ Wq) {
    __shared__ float As[128 * 36];
    __shared__ float Bs[32 * 132];
    const int tid = threadIdx.x;
    const int w   = tid >> 5;
    const int m0 = blockIdx.y * 128, n0 = blockIdx.x * 128;
    const int wm = (w >> 2) * 64, wn = (w & 3) * 32;

    wmma::fragment<wmma::accumulator, 16, 16, 8, float> acc[4][2];
#pragma unroll
    for (int i = 0; i < 4; i++)
#pragma unroll
        for (int j = 0; j < 2; j++) wmma::fill_fragment(acc[i][j], 0.f);

    for (int k0 = 0; k0 < H_; k0 += 32) {
#pragma unroll
        for (int it = 0; it < 4; it++) {     // A: 128 rows x 8 f4
            int idx = tid + it * 256;
            int r = idx >> 3, c = (idx & 7) * 4;
            float4 va = *reinterpret_cast<const float4*>(
                A + (size_t)(m0 + r) * H_ + k0 + c);
            As[r * 36 + c] = totf(va.x); As[r * 36 + c + 1] = totf(va.y);
            As[r * 36 + c + 2] = totf(va.z); As[r * 36 + c + 3] = totf(va.w);
        }
#pragma unroll
        for (int it = 0; it < 4; it++) {     // B: 32 rows x 32 f4 (128 n)
            int idx = tid + it * 256;
            int r = idx >> 5, c = (idx & 31) * 4;
            float4 vb = *reinterpret_cast<const float4*>(
                Wq + (size_t)(k0 + r) * H_ + n0 + c);
            Bs[r * 132 + c] = totf(vb.x); Bs[r * 132 + c + 1] = totf(vb.y);
            Bs[r * 132 + c + 2] = totf(vb.z); Bs[r * 132 + c + 3] = totf(vb.w);
        }
        __syncthreads();
#pragma unroll
        for (int kk = 0; kk < 4; kk++) {
            wmma::fragment<wmma::matrix_b, 16, 16, 8, wmma::precision::tf32, wmma::row_major> b[2];
#pragma unroll
            for (int j = 0; j < 2; j++)
                wmma::load_matrix_sync(b[j], Bs + kk * 8 * 132 + wn + j * 16, 132);
#pragma unroll
            for (int i = 0; i < 4; i++) {
                wmma::fragment<wmma::matrix_a, 16, 16, 8, wmma::precision::tf32, wmma::row_major> a;
                wmma::load_matrix_sync(a, As + (wm + i * 16) * 36 + kk * 8, 36);
#pragma unroll
                for (int j = 0; j < 2; j++) wmma::mma_sync(acc[i][j], a, b[j], acc[i][j]);
            }
        }
        __syncthreads();
    }
#pragma unroll
    for (int i = 0; i < 4; i++)
#pragma unroll
        for (int j = 0; j < 2; j++)
            wmma::store_matrix_sync(g_c2 + (size_t)(m0 + wm + i * 16) * H_ + n0 + wn + j * 16,
                                    acc[i][j], H_, wmma::mem_row_major);
}

// ---------------- persistent scan kernel (tf32 WMMA for L0/L1) --------------
// SMEM float offsets
#define SM_W0    0                          // 16 x 520
#define SM_W1    8320                       // 16 x 1040
#define SM_WOS   24960                      // 4 x 1024
#define SM_STAGE 29056                      // 32 x 520 (also k4 cat region 16384)
#define SM_PBUF  45696                      // 8 x 256 wmma partials
#define SM_GBUF  47744                      // 16 x 32
#define SM_CB    48256                      // 2 x 4 x 32
#define SM_B1    48512                      // 16
#define SM_PART  48528                      // 8 x 32
#define SMEM_FLOATS 48784
#define SMEM_BYTES  (SMEM_FLOATS * 4)

#define LDW0  520
#define LDW1  1040
#define LDST  520

__device__ __forceinline__ void gridbar(unsigned target) {
    __threadfence();
    __syncthreads();
    if (threadIdx.x == 0) {
        atomicAdd(&g_bar, 1u);
        volatile unsigned* vb = &g_bar;
        while (*vb < target) { }
    }
    __syncthreads();
}

// copy 32x512 row-major h into padded stage [b][520], rounding to tf32
__device__ __forceinline__ void stage_rows(float* stg, const float4* src, int tid) {
    for (int idx = tid; idx < 4096; idx += 256) {
        int b = idx >> 7, j = idx & 127;
        float4 v = __ldcg(&src[idx]);
        v.x = totf(v.x); v.y = totf(v.y); v.z = totf(v.z); v.w = totf(v.w);
        reinterpret_cast<float4*>(stg + b * LDST)[j] = v;
    }
}

__global__ void __launch_bounds__(256, 1)
k_scan(const float* __restrict__ Whh0, const float* __restrict__ Wih1,
       const float* __restrict__ Whh1, const float* __restrict__ bih,
       const float* __restrict__ bhh, const float* __restrict__ context,
       const float* __restrict__ Wout, const float* __restrict__ h0in,
       const float* __restrict__ c0in, float* __restrict__ out) {
    extern __shared__ float sm[];
    float*  W0s   = sm + SM_W0;
    float*  W1s   = sm + SM_W1;
    float*  Wos   = sm + SM_WOS;
    float*  stg   = sm + SM_STAGE;
    float4* stage4 = reinterpret_cast<float4*>(sm + SM_STAGE);   // k4 view (attn-out)
    float*  pbuf  = sm + SM_PBUF;
    float*  gbuf  = sm + SM_GBUF;
    float*  cb    = sm + SM_CB;
    float*  bias1 = sm + SM_B1;
    float*  part  = sm + SM_PART;

    const int cta = blockIdx.x;
    const int tid = threadIdx.x;
    const int w   = tid >> 5;
    const int lane = tid & 31;
    const int u0  = cta * UPC_;
    const int wn  = w & 1;            // n-tile (batch 16s)
    const int wkc = w >> 1;           // k-chunk (128s)

    // -------- prologue: weights -> SMEM (pre-rounded to tf32) --------------
    for (int idx = tid; idx < 16 * 128; idx += 256) {
        int r = idx >> 7, kq = idx & 127;
        int row = ((r >> 2) * H_) + u0 + (r & 3);
        float4 v = *reinterpret_cast<const float4*>(Whh0 + (size_t)row * H_ + kq * 4);
        v.x = totf(v.x); v.y = totf(v.y); v.z = totf(v.z); v.w = totf(v.w);
        reinterpret_cast<float4*>(W0s + r * LDW0)[kq] = v;
    }
    for (int idx = tid; idx < 16 * 256; idx += 256) {
        int r = idx >> 8, kq = idx & 255;
        int row = ((r >> 2) * H_) + u0 + (r & 3);
        const float* src = (kq < 128)
            ? (Wih1 + (size_t)row * H_ + kq * 4)
            : (Whh1 + (size_t)row * H_ + (kq - 128) * 4);
        float4 v = *reinterpret_cast<const float4*>(src);
        v.x = totf(v.x); v.y = totf(v.y); v.z = totf(v.z); v.w = totf(v.w);
        reinterpret_cast<float4*>(W1s + r * LDW1)[kq] = v;
    }
    for (int idx = tid; idx < 4 * 256; idx += 256) {     // Wos stays fp32
        int r = idx >> 8, kq = idx & 255;
        reinterpret_cast<float4*>(Wos + r * 1024)[kq] =
            *reinterpret_cast<const float4*>(Wout + (size_t)(u0 + r) * (2 * H_) + kq * 4);
    }
    if (tid < 16) {
        int row = ((tid >> 2) * H_) + u0 + (tid & 3);
        bias1[tid] = bih[G4_ + row] + bhh[G4_ + row];
    }
    {   // cell state: cb[l*128 + ul*32 + b]
        int l = tid >> 7, ul = (tid >> 5) & 3, b = tid & 31;
        cb[tid] = c0in[(size_t)l * B_ * H_ + (size_t)b * H_ + u0 + ul];
    }
    if (tid < 32) {   // initial h -> row-major global
        int b = tid;
#pragma unroll
        for (int ul = 0; ul < 4; ul++) {
            __stcg(&g_h0[0][b * H_ + u0 + ul], h0in[(size_t)b * H_ + u0 + ul]);
            __stcg(&g_h1[0][b * H_ + u0 + ul], h0in[(size_t)B_ * H_ + b * H_ + u0 + ul]);
        }
    }
    unsigned nbar = 0;
    gridbar(++nbar * CTAS_);

    // -------- main scan ----------------------------------------------------
    for (int t = 0; t < T_; t++) {
        const int p = t & 1;

        // ===== layer 0: gates = W0 (16x512) x h0^T (512x32), tf32 wmma =====
        stage_rows(stg, reinterpret_cast<const float4*>(g_h0[p]), tid);
        __syncthreads();
        {
            wmma::fragment<wmma::accumulator, 16, 16, 8, float> c;
            wmma::fill_fragment(c, 0.f);
#pragma unroll
            for (int kk = 0; kk < 16; kk++) {
                int k = wkc * 128 + kk * 8;
                wmma::fragment<wmma::matrix_a, 16, 16, 8, wmma::precision::tf32, wmma::row_major> a;
                wmma::fragment<wmma::matrix_b, 16, 16, 8, wmma::precision::tf32, wmma::col_major> b;
                wmma::load_matrix_sync(a, W0s + k, LDW0);
                wmma::load_matrix_sync(b, stg + (wn * 16) * LDST + k, LDST);
                wmma::mma_sync(c, a, b, c);
            }
            wmma::store_matrix_sync(pbuf + w * 256, c, 16, wmma::mem_row_major);
        }
        __syncthreads();
        for (int o = tid; o < 512; o += 256) {          // reduce 4 k-chunks
            int r = o >> 5, b = o & 31;
            float s = 0.f;
#pragma unroll
            for (int kc = 0; kc < 4; kc++)
                s += pbuf[((b >> 4) + 2 * kc) * 256 + r * 16 + (b & 15)];
            gbuf[r * 32 + b] = s;
        }
        __syncthreads();
        if (tid < 128) {
            int ul = tid >> 5, b = tid & 31, u = u0 + ul;
            const float* pre = g_pre0 + (size_t)t * G4_ * B_;
            float gi = sigf(gbuf[(0  + ul) * 32 + b] + __ldg(&pre[((size_t)0 * H_ + u) * B_ + b]));
            float gf = sigf(gbuf[(4  + ul) * 32 + b] + __ldg(&pre[((size_t)1 * H_ + u) * B_ + b]));
            float gg = tanhf(gbuf[(8  + ul) * 32 + b] + __ldg(&pre[((size_t)2 * H_ + u) * B_ + b]));
            float go = sigf(gbuf[(12 + ul) * 32 + b] + __ldg(&pre[((size_t)3 * H_ + u) * B_ + b]));
            float c = gf * cb[ul * 32 + b] + gi * gg;
            cb[ul * 32 + b] = c;
            float h = go * tanhf(c);
            __stcg(&g_h0[p ^ 1][b * H_ + u], h);
            if (t == T_ - 1) {
                out[OFF_HT + (size_t)b * H_ + u] = h;
                out[OFF_CT + (size_t)b * H_ + u] = c;
            }
        }
        gridbar(++nbar * CTAS_);

        // ===== layer 1: two K passes (x = h0new, then h1old), tf32 wmma =====
        {
            wmma::fragment<wmma::accumulator, 16, 16, 8, float> c;
            wmma::fill_fragment(c, 0.f);
#pragma unroll
            for (int pass = 0; pass < 2; pass++) {
                const float4* src = pass ? reinterpret_cast<const float4*>(g_h1[p])
                                         : reinterpret_cast<const float4*>(g_h0[p ^ 1]);
                stage_rows(stg, src, tid);
                __syncthreads();
                const int koff = pass * 512;
#pragma unroll
                for (int kk = 0; kk < 16; kk++) {
                    int k = wkc * 128 + kk * 8;
                    wmma::fragment<wmma::matrix_a, 16, 16, 8, wmma::precision::tf32, wmma::row_major> a;
                    wmma::fragment<wmma::matrix_b, 16, 16, 8, wmma::precision::tf32, wmma::col_major> b;
                    wmma::load_matrix_sync(a, W1s + koff + k, LDW1);
                    wmma::load_matrix_sync(b, stg + (wn * 16) * LDST + k, LDST);
                    wmma::mma_sync(c, a, b, c);
                }
                __syncthreads();   // stage reuse between passes
            }
            wmma::store_matrix_sync(pbuf + w * 256, c, 16, wmma::mem_row_major);
        }
        __syncthreads();
        for (int o = tid; o < 512; o += 256) {
            int r = o >> 5, b = o & 31;
            float s = 0.f;
#pragma unroll
            for (int kc = 0; kc < 4; kc++)
                s += pbuf[((b >> 4) + 2 * kc) * 256 + r * 16 + (b & 15)];
            gbuf[r * 32 + b] = s;
        }
        __syncthreads();
        if (tid < 128) {
            int ul = tid >> 5, b = tid & 31, u = u0 + ul;
            float gi = sigf(gbuf[(0  + ul) * 32 + b] + bias1[0  + ul]);
            float gf = sigf(gbuf[(4  + ul) * 32 + b] + bias1[4  + ul]);
            float gg = tanhf(gbuf[(8  + ul) * 32 + b] + bias1[8  + ul]);
            float go = sigf(gbuf[(12 + ul) * 32 + b] + bias1[12 + ul]);
            float c = gf * cb[128 + ul * 32 + b] + gi * gg;
            cb[128 + ul * 32 + b] = c;
            float h = go * tanhf(c);
            __stcg(&g_h1[p ^ 1][b * H_ + u], h);
            if (t == T_ - 1) {
                out[OFF_HT + (size_t)B_ * H_ + (size_t)b * H_ + u] = h;
                out[OFF_CT + (size_t)B_ * H_ + (size_t)b * H_ + u] = c;
            }
        }
        gridbar(++nbar * CTAS_);

        // ===== attention (CTAs 0..31, one batch element each) =====
        if (cta < B_) {
            float* qs  = stg;                  // 512
            float* sc  = qs + 512;             // 64
            float* att = sc + 64;              // 64
            const float4* h1row = reinterpret_cast<const float4*>(g_h1[p ^ 1] + cta * H_);
            for (int q = tid; q < 128; q += 256)
                reinterpret_cast<float4*>(qs)[q] = __ldcg(&h1row[q]);
            __syncthreads();
            for (int s = w; s < S_; s += 8) {
                const float* c2 = g_c2 + (size_t)(cta * S_ + s) * H_;
                float a = 0.f;
                for (int k = lane; k < H_; k += 32) a += c2[k] * qs[k];
#pragma unroll
                for (int off = 16; off; off >>= 1) a += __shfl_xor_sync(0xffffffffu, a, off);
                if (lane == 0) sc[s] = a;
            }
            __syncthreads();
            if (tid < 32) {
                float v0 = sc[tid], v1 = sc[tid + 32];
                float m = fmaxf(v0, v1);
#pragma unroll
                for (int off = 16; off; off >>= 1) m = fmaxf(m, __shfl_xor_sync(0xffffffffu, m, off));
                float e0 = __expf(v0 - m), e1 = __expf(v1 - m);
                float s2 = e0 + e1;
#pragma unroll
                for (int off = 16; off; off >>= 1) s2 += __shfl_xor_sync(0xffffffffu, s2, off);
                float inv = 1.f / s2;
                att[tid] = e0 * inv; att[tid + 32] = e1 * inv;
                if (t == T_ - 1) {
                    out[OFF_ATTN + cta * S_ + tid]      = e0 * inv;
                    out[OFF_ATTN + cta * S_ + tid + 32] = e1 * inv;
                }
            }
            __syncthreads();
            for (int h = tid; h < H_; h += 256) {
                float a = 0.f;
                const float* cx = context + (size_t)cta * S_ * H_ + h;
#pragma unroll 8
                for (int s = 0; s < S_; s++) a += att[s] * cx[(size_t)s * H_];
                __stcg(&reinterpret_cast<float*>(g_cat4)[((h >> 2) * 32 + cta) * 4 + (h & 3)], a);
                int h2 = H_ + h;
                __stcg(&reinterpret_cast<float*>(g_cat4)[((h2 >> 2) * 32 + cta) * 4 + (h2 & 3)], qs[h]);
            }
        }
        gridbar(++nbar * CTAS_);

        // ===== attention-out (scalar, k4 stage): warp = (row=w&3, sub=w>>2) =====
        {
            float oa = 0.f, ob = 0.f;
            const int row = w & 3, sub = w >> 2;
            for (int half = 0; half < 2; half++) {
                for (int i = tid; i < 4096; i += 256)
                    stage4[i] = __ldcg(&g_cat4[half * 4096 + i]);
                __syncthreads();
                const float4* wr = reinterpret_cast<const float4*>(Wos + row * 1024 + half * H_);
                const int i0 = sub * 64;
#pragma unroll 4
                for (int i = 0; i < 64; i++) {
                    float4 h = stage4[(i0 + i) * 32 + lane];
                    float4 x = wr[i0 + i];
                    oa += x.x * h.x + x.y * h.y;
                    ob += x.z * h.z + x.w * h.w;
                }
                __syncthreads();
            }
            part[w * 32 + lane] = oa + ob;
        }
        __syncthreads();
        if (tid < 128) {
            int r = tid >> 5, b = tid & 31;
            float v = tanhf(part[r * 32 + b] + part[(r + 4) * 32 + b]);
            g_outs_bf[((size_t)t * B_ + b) * H_ + u0 + r] = __float2bfloat16(v);
        }
        __syncthreads();   // protect stage before next step's restage
    }
}

// ---------------- vocab GEMM: logits = outs_bf @ wlin_bf^T (k-tile 32) ------
__global__ void __launch_bounds__(256)
k_wmma(float* __restrict__ C) {
    __shared__ __align__(16) __nv_bfloat16 As[128 * 40];
    __shared__ __align__(16) __nv_bfloat16 Bs[128 * 40];
    const int m0 = blockIdx.y * 128, n0 = blockIdx.x * 128;
    const int tid = threadIdx.x;                  // 256
    const int wid = tid >> 5;
    const int wm = (wid >> 2) * 64, wn = (wid & 3) * 32;
    wmma::fragment<wmma::accumulator, 16, 16, 16, float> acc[4][2];
#pragma unroll
    for (int i = 0; i < 4; i++)
#pragma unroll
        for (int j = 0; j < 2; j++) wmma::fill_fragment(acc[i][j], 0.f);
    const int r = tid >> 1;
    const int c = (tid & 1) * 16;
    for (int k0 = 0; k0 < D_; k0 += 32) {
#pragma unroll
        for (int q = 0; q < 2; q++) {
            *reinterpret_cast<uint4*>(&As[r * 40 + c + q * 8]) =
                *reinterpret_cast<const uint4*>(&g_outs_bf[(size_t)(m0 + r) * D_ + k0 + c + q * 8]);
            *reinterpret_cast<uint4*>(&Bs[r * 40 + c + q * 8]) =
                *reinterpret_cast<const uint4*>(&g_wlin_bf[(size_t)(n0 + r) * D_ + k0 + c + q * 8]);
        }
        __syncthreads();
#pragma unroll
        for (int sub = 0; sub < 2; sub++) {
            wmma::fragment<wmma::matrix_b, 16, 16, 16, __nv_bfloat16, wmma::col_major> bf[2];
#pragma unroll
            for (int j = 0; j < 2; j++)
                wmma::load_matrix_sync(bf[j], &Bs[(wn + j * 16) * 40 + sub * 16], 40);
#pragma unroll
            for (int i = 0; i < 4; i++) {
                wmma::fragment<wmma::matrix_a, 16, 16, 16, __nv_bfloat16, wmma::row_major> af;
                wmma::load_matrix_sync(af, &As[(wm + i * 16) * 40 + sub * 16], 40);
#pragma unroll
                for (int j = 0; j < 2; j++) wmma::mma_sync(acc[i][j], af, bf[j], acc[i][j]);
            }
        }
        __syncthreads();
    }
#pragma unroll
    for (int i = 0; i < 4; i++)
#pragma unroll
        for (int j = 0; j < 2; j++)
            wmma::store_matrix_sync(C + (size_t)(m0 + wm + i * 16) * V_ + n0 + wn + j * 16,
                                    acc[i][j], V_, wmma::mem_row_major);
}

// ---------------- log_softmax (adds b_lin, in-place over d_out rows) --------
__global__ void k_logsoftmax(float* __restrict__ logits, const float* __restrict__ b_lin) {
    const int row = blockIdx.x;
    float* p = logits + (size_t)row * V_;
    const int tid = threadIdx.x;
    float m = -1e30f, s = 0.f;
    for (int v = tid; v < V_; v += 256) {
        float x = p[v] + b_lin[v];
        if (x > m) { s = s * __expf(m - x) + 1.f; m = x; }
        else       { s += __expf(x - m); }
    }
    __shared__ float sm[256], ss[256];
    sm[tid] = m; ss[tid] = s;
    __syncthreads();
    for (int off = 128; off; off >>= 1) {
        if (tid < off) {
            float m2 = sm[tid + off], s2 = ss[tid + off];
            float M = fmaxf(sm[tid], m2);
            ss[tid] = ss[tid] * __expf(sm[tid] - M) + s2 * __expf(m2 - M);
            sm[tid] = M;
        }
        __syncthreads();
    }
    float lse = sm[0] + logf(ss[0]);
    for (int v = tid; v < V_; v += 256)
        p[v] = p[v] + b_lin[v] - lse;
}

// ---------------- host driver ----------------------------------------------
extern "C" void kernel_launch(void* const* d_in, const int* in_sizes, int n_in,
                              void* d_out, int out_size) {
    const int*   tokens     = (const int*)d_in[0];
    const float* h0         = (const float*)d_in[1];
    const float* c0         = (const float*)d_in[2];
    const float* context    = (const float*)d_in[3];
    const float* embedding  = (const float*)d_in[4];
    const float* Wih        = (const float*)d_in[5];
    const float* Whh        = (const float*)d_in[6];
    const float* bih        = (const float*)d_in[7];
    const float* bhh        = (const float*)d_in[8];
    const float* W_attn_in  = (const float*)d_in[9];
    const float* W_attn_out = (const float*)d_in[10];
    const float* W_lin      = (const float*)d_in[11];
    const float* b_lin      = (const float*)d_in[12];
    float* out = (float*)d_out;

    cudaFuncSetAttribute(k_scan, cudaFuncAttributeMaxDynamicSharedMemorySize, SMEM_BYTES);

    const float* Wih1 = Wih + (size_t)G4_ * D_;
    const float* Whh1 = Whh + (size_t)G4_ * H_;

    k_reset<<<1, 1>>>();
    k_convert_wlin<<<(V_ * D_ / 4 + 255) / 256, 256>>>(W_lin);
    k_gemm_pre<<<dim3(G4_ / 128, MR_ / 128), 256>>>(tokens, embedding, Wih, bih, bhh);
    k_c2<<<dim3(H_ / 128, (B_ * S_) / 128), 256>>>(context, W_attn_in);
    k_scan<<<CTAS_, 256, SMEM_BYTES>>>(Whh, Wih1, Whh1, bih, bhh, context,
                                       W_attn_out, h0, c0, out);
    k_wmma<<<dim3(V_ / 128, MR_ / 128), 256>>>(out);
    k_logsoftmax<<<MR_, 256>>>(out, b_lin);
}